// round 11
// baseline (speedup 1.0000x reference)
#include <cuda_runtime.h>
#include <cuda_bf16.h>
#include <cuda_fp16.h>
#include <cstdint>

#define S_   38
#define R_   340
#define HC_  128
#define SC_  4
#define RC_  3
#define NO_  7
#define L_   4
#define BMAX 512
#define NMAX (BMAX * (S_ + R_))   // 193536
#define EMAX 3072000

// ---------------- scratch (device globals; no allocation allowed) ----------------
__device__ __nv_bfloat16 d_Xh[NMAX * HC_];      // X split hi (49.5 MB) — residual hi
__device__ __nv_bfloat16 d_Xl[NMAX * HC_];      // X split lo (49.5 MB) — residual lo
__device__ __half        d_XWh[NMAX * HC_];     // X @ W in fp16 (49.5 MB, L2-resident)
__device__ int   d_degi[NMAX];
__device__ float d_dinv[NMAX];
__device__ int   d_offs[NMAX];
__device__ int   d_curs[NMAX];
__device__ int   d_bsum[512];
__device__ uint2 d_edge[EMAX];                  // packed (src, norm-bits) per CSR slot
__device__ float d_stats[16];                   // zero-init; re-zeroed by k_prep each call
__device__ float d_pre[16];
__device__ float d_O[BMAX * NO_];
__device__ float d_pooled[NMAX];
// pre-split weights in blocked-swizzled MMA layout (bf16 hi/lo), 32 KB per layer each
__device__ __align__(16) unsigned char d_Wh[L_][32768];
__device__ __align__(16) unsigned char d_Wl[L_][32768];

__device__ __forceinline__ float leaky(float x) { return x > 0.f ? x : 0.2f * x; }

// ================= tcgen05 helpers (verified rounds 5/8/9/10) =============
__device__ __forceinline__ uint32_t smem_u32(const void* p) {
    uint32_t a;
    asm("{ .reg .u64 t; cvta.to.shared.u64 t, %1; cvt.u32.u64 %0, t; }" : "=r"(a) : "l"(p));
    return a;
}
__device__ __forceinline__ uint32_t elect_one() {
    uint32_t pred;
    asm volatile("{\n\t.reg .pred p;\n\telect.sync _|p, 0xFFFFFFFF;\n\tselp.b32 %0, 1, 0, p;\n\t}" : "=r"(pred));
    return pred;
}
#define TCG_ALLOC(dst_smem, n) \
    asm volatile("tcgen05.alloc.cta_group::1.sync.aligned.shared::cta.b32 [%0], %1;" \
                 :: "r"(dst_smem), "r"((uint32_t)(n)) : "memory")
#define TCG_DEALLOC(tmem, n) \
    asm volatile("tcgen05.dealloc.cta_group::1.sync.aligned.b32 %0, %1;" :: "r"(tmem), "r"((uint32_t)(n)))
#define TCG_RELINQ() asm volatile("tcgen05.relinquish_alloc_permit.cta_group::1.sync.aligned;")
#define TCG_COMMIT(mbar) \
    asm volatile("tcgen05.commit.cta_group::1.mbarrier::arrive::one.shared::cluster.b64 [%0];" \
                 :: "r"(mbar) : "memory")
#define TCG_FENCE_BEFORE() asm volatile("tcgen05.fence::before_thread_sync;" ::: "memory")
#define TCG_FENCE_AFTER()  asm volatile("tcgen05.fence::after_thread_sync;" ::: "memory")
#define TCG_WAIT_LD() asm volatile("tcgen05.wait::ld.sync.aligned;" ::: "memory")
#define FENCE_ASYNC_SHARED() asm volatile("fence.proxy.async.shared::cta;" ::: "memory")
#define MBAR_INIT(mbar, cnt) \
    asm volatile("mbarrier.init.shared.b64 [%0], %1;" :: "r"(mbar), "r"((uint32_t)(cnt)) : "memory")
#define MBAR_INVAL(mbar) asm volatile("mbarrier.inval.shared.b64 [%0];" :: "r"(mbar) : "memory")

__device__ __forceinline__ void mbar_wait_parity(uint32_t mbar, uint32_t parity) {
    uint32_t done;
    asm volatile("{\n\t.reg .pred p;\n\t"
                 "mbarrier.try_wait.parity.acquire.cta.shared::cta.b64 p, [%1], %2;\n\t"
                 "selp.b32 %0, 1, 0, p;\n\t}"
                 : "=r"(done) : "r"(mbar), "r"(parity) : "memory");
    if (!done) {
        asm volatile("{\n\t.reg .pred P1;\n\t"
                     "WL_%=:\n\t"
                     "mbarrier.try_wait.parity.acquire.cta.shared::cta.b64 P1, [%0], %1, 0x989680;\n\t"
                     "@P1 bra.uni WD_%=;\n\t"
                     "bra.uni WL_%=;\n\t"
                     "WD_%=:\n\t}"
                     :: "r"(mbar), "r"(parity) : "memory");
    }
}

#define TCG_LD_32X32B_X32(r, tmem) \
    asm volatile( \
        "tcgen05.ld.sync.aligned.32x32b.x32.b32 " \
        "{%0, %1, %2, %3, %4, %5, %6, %7, " \
        " %8, %9, %10, %11, %12, %13, %14, %15, " \
        " %16, %17, %18, %19, %20, %21, %22, %23, " \
        " %24, %25, %26, %27, %28, %29, %30, %31}, [%32];" \
        : "=r"((r)[0]),  "=r"((r)[1]),  "=r"((r)[2]),  "=r"((r)[3]), \
          "=r"((r)[4]),  "=r"((r)[5]),  "=r"((r)[6]),  "=r"((r)[7]), \
          "=r"((r)[8]),  "=r"((r)[9]),  "=r"((r)[10]), "=r"((r)[11]), \
          "=r"((r)[12]), "=r"((r)[13]), "=r"((r)[14]), "=r"((r)[15]), \
          "=r"((r)[16]), "=r"((r)[17]), "=r"((r)[18]), "=r"((r)[19]), \
          "=r"((r)[20]), "=r"((r)[21]), "=r"((r)[22]), "=r"((r)[23]), \
          "=r"((r)[24]), "=r"((r)[25]), "=r"((r)[26]), "=r"((r)[27]), \
          "=r"((r)[28]), "=r"((r)[29]), "=r"((r)[30]), "=r"((r)[31]) \
        : "r"(tmem))

// SW128 K-major SMEM descriptor (layout=2, version=1, SBO=64, LBO=1)
static __device__ __forceinline__ uint64_t make_desc(uint32_t addr) {
    return ((uint64_t)2 << 61) | ((uint64_t)1 << 46) | ((uint64_t)64 << 32)
         | ((uint64_t)1 << 16) | (uint64_t)((addr >> 4) & 0x3FFF);
}
__device__ __forceinline__ uint32_t sw128(uint32_t off) { return off ^ ((off >> 3) & 0x70); }

// blocked-atom byte offset for bf16 K-major tile, 128 rows x 128 K-cols
__device__ __forceinline__ uint32_t bf16_off(int row, int col) {
    uint32_t off = (uint32_t)(((row >> 3) + (col >> 6) * 16) * 1024 + (row & 7) * 128 + (col & 63) * 2);
    return sw128(off);
}

#if defined(__CUDA_ARCH_FEAT_SM103_ALL) || !defined(__CUDA_ARCH__)
__device__ __forceinline__ void mma_f16_ss(uint32_t d, uint64_t ad, uint64_t bd,
                                           uint32_t idesc, bool acc) {
    uint32_t en = acc ? 1u : 0u;
    asm volatile(
        "{\n\t.reg .pred p;\n\tsetp.ne.u32 p, %5, 0;\n\t"
        "tcgen05.mma.cta_group::1.kind::f16 [%0], %1, %2, %3, {%4, %4, %4, %4}, p;\n\t}"
        :: "r"(d), "l"(ad), "l"(bd), "r"(idesc), "r"(0u), "r"(en) : "memory");
}
#endif

// idesc: dtype=F32, atype=BF16, btype=BF16, N=128, M=128
#define MMA_IDESC ((1u << 4) | (1u << 7) | (1u << 10) | (16u << 17) | (8u << 24))

// split helper: fp32 -> (hi, lo) bf16
__device__ __forceinline__ void bsplit(float v, __nv_bfloat16& h, __nv_bfloat16& l) {
    h = __float2bfloat16_rn(v);
    l = __float2bfloat16_rn(v - __bfloat162float(h));
}

// ---------------- batchnorm stats (d_stats zeroed by k_prep / static init) --------
__global__ void k_stats_s(const float* __restrict__ sx, int rows) {
    const float4* v4 = (const float4*)sx;
    float s0 = 0, s1 = 0, s2 = 0, s3 = 0, q0 = 0, q1 = 0, q2 = 0, q3 = 0;
    for (int r = blockIdx.x * blockDim.x + threadIdx.x; r < rows; r += gridDim.x * blockDim.x) {
        float4 v = v4[r];
        s0 += v.x; q0 += v.x * v.x;
        s1 += v.y; q1 += v.y * v.y;
        s2 += v.z; q2 += v.z * v.z;
        s3 += v.w; q3 += v.w * v.w;
    }
    #pragma unroll
    for (int off = 16; off > 0; off >>= 1) {
        s0 += __shfl_down_sync(0xffffffffu, s0, off);
        s1 += __shfl_down_sync(0xffffffffu, s1, off);
        s2 += __shfl_down_sync(0xffffffffu, s2, off);
        s3 += __shfl_down_sync(0xffffffffu, s3, off);
        q0 += __shfl_down_sync(0xffffffffu, q0, off);
        q1 += __shfl_down_sync(0xffffffffu, q1, off);
        q2 += __shfl_down_sync(0xffffffffu, q2, off);
        q3 += __shfl_down_sync(0xffffffffu, q3, off);
    }
    if ((threadIdx.x & 31) == 0) {
        atomicAdd(&d_stats[0], s0); atomicAdd(&d_stats[1], s1);
        atomicAdd(&d_stats[2], s2); atomicAdd(&d_stats[3], s3);
        atomicAdd(&d_stats[4], q0); atomicAdd(&d_stats[5], q1);
        atomicAdd(&d_stats[6], q2); atomicAdd(&d_stats[7], q3);
    }
}

__global__ void k_stats_r(const float* __restrict__ rx, int rows) {
    const float4* v4 = (const float4*)rx;
    float s0 = 0, s1 = 0, s2 = 0, q0 = 0, q1 = 0, q2 = 0;
    for (int r = blockIdx.x * blockDim.x + threadIdx.x; r < rows; r += gridDim.x * blockDim.x) {
        float4 v = v4[r * 2];
        s0 += v.x; q0 += v.x * v.x;
        s1 += v.y; q1 += v.y * v.y;
        s2 += v.z; q2 += v.z * v.z;
    }
    #pragma unroll
    for (int off = 16; off > 0; off >>= 1) {
        s0 += __shfl_down_sync(0xffffffffu, s0, off);
        s1 += __shfl_down_sync(0xffffffffu, s1, off);
        s2 += __shfl_down_sync(0xffffffffu, s2, off);
        q0 += __shfl_down_sync(0xffffffffu, q0, off);
        q1 += __shfl_down_sync(0xffffffffu, q1, off);
        q2 += __shfl_down_sync(0xffffffffu, q2, off);
    }
    if ((threadIdx.x & 31) == 0) {
        atomicAdd(&d_stats[8],  s0); atomicAdd(&d_stats[9],  s1);
        atomicAdd(&d_stats[10], s2); atomicAdd(&d_stats[11], q0);
        atomicAdd(&d_stats[12], q1); atomicAdd(&d_stats[13], q2);
    }
}

// computes bn scale/shift, then re-zeroes d_stats for the next graph replay
__global__ void k_prep(const float* __restrict__ bsw, const float* __restrict__ bsb,
                       const float* __restrict__ brw, const float* __restrict__ brb,
                       int ns, int nr) {
    int t = threadIdx.x;
    if (t < 4) {
        float m = d_stats[t] / (float)ns;
        float var = d_stats[4 + t] / (float)ns - m * m;
        float sc = rsqrtf(var + 1e-5f) * bsw[t];
        d_pre[t] = sc;
        d_pre[4 + t] = bsb[t] - m * sc;
    } else if (t < 7) {
        int c = t - 4;
        float m = d_stats[8 + c] / (float)nr;
        float var = d_stats[11 + c] / (float)nr - m * m;
        float sc = rsqrtf(var + 1e-5f) * brw[c];
        d_pre[8 + c] = sc;
        d_pre[11 + c] = brb[c] - m * sc;
    }
    __syncthreads();
    if (t < 16) d_stats[t] = 0.f;
}

// --------- feature encoder + o-branch merged: blocks [0,n) feat, [n, n+Bn) o ------
__global__ void k_featO(const float* __restrict__ sx, const float* __restrict__ rx,
                        const float* __restrict__ wsl, const float* __restrict__ wrl,
                        const float* __restrict__ w1, const float* __restrict__ b1,
                        const float* __restrict__ w2, const float* __restrict__ b2,
                        int n) {
    __shared__ float sh[HC_];
    int h = threadIdx.x;
    if ((int)blockIdx.x < n) {
        int node = blockIdx.x;
        int b = node / (S_ + R_);
        int pos = node - b * (S_ + R_);
        float acc = 0.f;
        if (pos < S_) {
            int i = b * S_ + pos;
            #pragma unroll
            for (int c = 0; c < SC_; c++) {
                float xn = __ldg(sx + i * SC_ + c) * d_pre[c] + d_pre[4 + c];
                acc += xn * __ldg(wsl + c * HC_ + h);
            }
        } else {
            int ri = b * R_ + (pos - S_);
            #pragma unroll
            for (int c = 0; c < RC_; c++) {
                float xn = __ldg(rx + ri * (RC_ + 5) + c) * d_pre[8 + c] + d_pre[11 + c];
                acc += xn * __ldg(wrl + c * HC_ + h);
            }
        }
        float v = leaky(acc);
        __nv_bfloat16 hi, lo;
        bsplit(v, hi, lo);
        d_Xh[node * HC_ + h] = hi;
        d_Xl[node * HC_ + h] = lo;
    } else {
        int b = blockIdx.x - n;
        float acc = b1[h];
        #pragma unroll
        for (int c = 0; c < 5; c++)
            acc += __ldg(rx + (size_t)(b * R_) * (RC_ + 5) + RC_ + c) * __ldg(w1 + c * HC_ + h);
        sh[h] = leaky(acc);
        __syncthreads();
        if (h < NO_) {
            float o = b2[h];
            #pragma unroll 8
            for (int k = 0; k < HC_; k++) o += sh[k] * __ldg(w2 + k * NO_ + h);
            d_O[b * NO_ + h] = o;
        }
    }
}

// ---------------- W split precompute (once; all layers) ----------------
__global__ void k_wsplit(const float* __restrict__ conv_w) {
    int l = blockIdx.x;
    const float* W = conv_w + (size_t)l * HC_ * HC_;
    for (int i = threadIdx.x; i < HC_ * HC_; i += blockDim.x) {
        int k = i >> 7, nn = i & 127;
        float v = __ldg(W + k * 128 + nn);
        __nv_bfloat16 h, lo;
        bsplit(v, h, lo);
        uint32_t off = bf16_off(nn, k);   // B[n][k] = W[k][n]
        *(__nv_bfloat16*)(d_Wh[l] + off) = h;
        *(__nv_bfloat16*)(d_Wl[l] + off) = lo;
    }
}

// ---------------- init / degree / CSR ----------------
__global__ void k_zero(int n) {
    int i = blockIdx.x * blockDim.x + threadIdx.x;
    if (i < n) d_degi[i] = 0;
}

__global__ void k_count(const int* __restrict__ dst, int E) {
    int e = blockIdx.x * blockDim.x + threadIdx.x;
    if (e < E) atomicAdd(&d_degi[dst[e]], 1);
}

// scan1 also emits dinv (folded former k_dinv pass)
__global__ void k_scan1(int n) {
    __shared__ int sh[512];
    int t = threadIdx.x;
    int g = blockIdx.x * 512 + t;
    int v = (g < n) ? d_degi[g] : 0;
    if (g < n) d_dinv[g] = rsqrtf((float)(v + 1));
    sh[t] = v;
    __syncthreads();
    #pragma unroll
    for (int off = 1; off < 512; off <<= 1) {
        int a = sh[t];
        int b = (t >= off) ? sh[t - off] : 0;
        __syncthreads();
        sh[t] = a + b;
        __syncthreads();
    }
    if (g < n) d_offs[g] = sh[t] - v;
    if (t == 511) d_bsum[blockIdx.x] = sh[511];
}

__global__ void k_scan2(int nb) {
    __shared__ int sh[512];
    int t = threadIdx.x;
    int v = (t < nb) ? d_bsum[t] : 0;
    sh[t] = v;
    __syncthreads();
    #pragma unroll
    for (int off = 1; off < 512; off <<= 1) {
        int a = sh[t];
        int b = (t >= off) ? sh[t - off] : 0;
        __syncthreads();
        sh[t] = a + b;
        __syncthreads();
    }
    if (t < nb) d_bsum[t] = sh[t] - v;
}

__global__ void k_scan3(int n) {
    int g = blockIdx.x * blockDim.x + threadIdx.x;
    if (g < n) {
        int o = d_offs[g] + d_bsum[g >> 9];
        d_offs[g] = o;
        d_curs[g] = o;
    }
}

__global__ void k_fill(const int* __restrict__ src, const int* __restrict__ dst, int E) {
    int e = blockIdx.x * blockDim.x + threadIdx.x;
    if (e < E) {
        int s = src[e], d = dst[e];
        int p = atomicAdd(&d_curs[d], 1);
        float nw = d_dinv[s] * d_dinv[d];
        d_edge[p] = make_uint2((uint32_t)s, __float_as_uint(nw));
    }
}

// =============== persistent pipelined tcgen05 bf16x3 GEMM: XWh = fp16(X @ W) ======
__global__ void __launch_bounds__(128) k_mma(const float* __restrict__ W, int layer, int n) {
    extern __shared__ char dyn_smem[];
#if defined(__CUDA_ARCH_FEAT_SM103_ALL) || !defined(__CUDA_ARCH__)
    __shared__ uint32_t s_tmem[2];
    __shared__ __align__(8) unsigned long long s_mbar[2];

    char* base = (char*)(((uintptr_t)dyn_smem + 1023) & ~(uintptr_t)1023);
    char* A0h = base;
    char* A0l = base + 32768;
    char* A1h = base + 65536;
    char* A1l = base + 98304;
    char* Bh  = base + 131072;
    char* Bl  = base + 163840;   // total 192 KB

    int tid = threadIdx.x, wid = tid >> 5, lane = tid & 31;

    if (wid == 0) TCG_ALLOC(smem_u32(s_tmem), 256);
    if (tid == 0) {
        MBAR_INIT(smem_u32(&s_mbar[0]), 1);
        MBAR_INIT(smem_u32(&s_mbar[1]), 1);
    }
    __syncthreads();
    uint32_t tmem;
    asm volatile("ld.shared.b32 %0, [%1];" : "=r"(tmem) : "r"(smem_u32(s_tmem)));

    // stage pre-split W (coalesced uint4 copy, once per CTA)
    {
        const uint4* gh = (const uint4*)d_Wh[layer];
        const uint4* gl = (const uint4*)d_Wl[layer];
        uint4* sh = (uint4*)Bh;
        uint4* sl = (uint4*)Bl;
        for (int i = tid; i < 2048; i += 128) { sh[i] = gh[i]; sl[i] = gl[i]; }
    }

    const uint64_t bdh = make_desc(smem_u32(Bh));
    const uint64_t bdl = make_desc(smem_u32(Bl));
    const uint4* GXh = (const uint4*)d_Xh;   // row = 16 uint4 (128 bf16)
    const uint4* GXl = (const uint4*)d_Xl;
    __half* XWh = d_XWh;

    int tiles = (n + 127) >> 7;
    uint32_t ph0 = 0, ph1 = 0;
    int j = 0, prev_t = -1;

    for (int t = blockIdx.x; t < tiles; t += gridDim.x, j++) {
        int buf = j & 1;
        char* Ah = buf ? A1h : A0h;
        char* Al = buf ? A1l : A0l;
        int row0 = t << 7;

        // --- stage A tile: swizzled uint4 copy, streaming loads (no L2 pollution) ---
        #pragma unroll 4
        for (int i = tid; i < 2048; i += 128) {          // 128 rows x 16 quads
            int row = i >> 4, q = i & 15;
            uint4 vh = make_uint4(0u, 0u, 0u, 0u), vl = vh;
            if (row0 + row < n) {
                size_t gi = (size_t)(row0 + row) * 16 + q;
                vh = __ldcs(GXh + gi);
                vl = __ldcs(GXl + gi);
            }
            uint32_t off = bf16_off(row, q * 8);
            *(uint4*)(Ah + off) = vh;
            *(uint4*)(Al + off) = vl;
        }
        TCG_FENCE_BEFORE();
        __syncthreads();

        // --- wait for MMA[j-1] ---
        if (j > 0) {
            if (buf) { mbar_wait_parity(smem_u32(&s_mbar[0]), ph0); ph0 ^= 1; }
            else     { mbar_wait_parity(smem_u32(&s_mbar[1]), ph1); ph1 ^= 1; }
            TCG_FENCE_AFTER();
        }

        // --- issue MMA[j] ---
        if (wid == 0) {
            TCG_FENCE_AFTER();
            if (elect_one()) {
                FENCE_ASYNC_SHARED();
                uint64_t adh = make_desc(smem_u32(Ah));
                uint64_t adl = make_desc(smem_u32(Al));
                uint32_t D = tmem + buf * 128;
                #pragma unroll
                for (int s = 0; s < 8; s++) {
                    uint64_t off = (uint64_t)((s & 3) * 2 + (s >> 2) * 1024);
                    mma_f16_ss(D, adh + off, bdh + off, MMA_IDESC, s > 0);
                }
                #pragma unroll
                for (int s = 0; s < 8; s++) {
                    uint64_t off = (uint64_t)((s & 3) * 2 + (s >> 2) * 1024);
                    mma_f16_ss(D, adl + off, bdh + off, MMA_IDESC, true);
                }
                #pragma unroll
                for (int s = 0; s < 8; s++) {
                    uint64_t off = (uint64_t)((s & 3) * 2 + (s >> 2) * 1024);
                    mma_f16_ss(D, adh + off, bdl + off, MMA_IDESC, true);
                }
                TCG_COMMIT(smem_u32(&s_mbar[buf]));
            }
        }

        // --- epilogue for tile j-1 (overlaps MMA[j]); fp16 output ---
        if (j > 0) {
            int prow = (prev_t << 7) + wid * 32 + lane;
            uint32_t Dp = tmem + (1 - buf) * 128;
            uint32_t r[32];
            #pragma unroll
            for (int c0 = 0; c0 < 128; c0 += 32) {
                TCG_LD_32X32B_X32(r, Dp + c0);
                TCG_WAIT_LD();
                if (prow < n) {
                    uint32_t h2[16];
                    #pragma unroll
                    for (int k = 0; k < 16; k++) {
                        __half2 p = __floats2half2_rn(__uint_as_float(r[2 * k]),
                                                      __uint_as_float(r[2 * k + 1]));
                        h2[k] = *(uint32_t*)&p;
                    }
                    uint4* dst = (uint4*)(XWh + (size_t)prow * 128 + c0);
                    dst[0] = make_uint4(h2[0], h2[1], h2[2], h2[3]);
                    dst[1] = make_uint4(h2[4], h2[5], h2[6], h2[7]);
                    dst[2] = make_uint4(h2[8], h2[9], h2[10], h2[11]);
                    dst[3] = make_uint4(h2[12], h2[13], h2[14], h2[15]);
                }
            }
            TCG_FENCE_BEFORE();
        }
        prev_t = t;
    }

    // --- drain last tile ---
    if (j > 0) {
        int buf = (j - 1) & 1;
        if (buf) { mbar_wait_parity(smem_u32(&s_mbar[1]), ph1); ph1 ^= 1; }
        else     { mbar_wait_parity(smem_u32(&s_mbar[0]), ph0); ph0 ^= 1; }
        TCG_FENCE_AFTER();
        int prow = (prev_t << 7) + wid * 32 + lane;
        uint32_t Dp = tmem + buf * 128;
        uint32_t r[32];
        #pragma unroll
        for (int c0 = 0; c0 < 128; c0 += 32) {
            TCG_LD_32X32B_X32(r, Dp + c0);
            TCG_WAIT_LD();
            if (prow < n) {
                uint32_t h2[16];
                #pragma unroll
                for (int k = 0; k < 16; k++) {
                    __half2 p = __floats2half2_rn(__uint_as_float(r[2 * k]),
                                                  __uint_as_float(r[2 * k + 1]));
                    h2[k] = *(uint32_t*)&p;
                }
                uint4* dst = (uint4*)(XWh + (size_t)prow * 128 + c0);
                dst[0] = make_uint4(h2[0], h2[1], h2[2], h2[3]);
                dst[1] = make_uint4(h2[4], h2[5], h2[6], h2[7]);
                dst[2] = make_uint4(h2[8], h2[9], h2[10], h2[11]);
                dst[3] = make_uint4(h2[12], h2[13], h2[14], h2[15]);
            }
        }
        TCG_FENCE_BEFORE();
    }
    __syncthreads();
    if (wid == 0) {
        if (elect_one()) {
            MBAR_INVAL(smem_u32(&s_mbar[0]));
            MBAR_INVAL(smem_u32(&s_mbar[1]));
        }
        TCG_RELINQ();
        TCG_DEALLOC(tmem, 256);
    }
#else
    // fp32 fallback for the non-'a' gencode pass (never selected at runtime on GB300)
    float* Ws = (float*)(((uintptr_t)dyn_smem + 1023) & ~(uintptr_t)1023);  // 64 KB
    int tid = threadIdx.x;
    for (int i = tid; i < 128 * 128; i += 128) Ws[i] = __ldg(W + i);
    __syncthreads();
    int tiles = (n + 127) >> 7;
    for (int t = blockIdx.x; t < tiles; t += gridDim.x) {
        int row = (t << 7) + tid;
        if (row < n) {
            for (int c0 = 0; c0 < 128; c0 += 16) {
                float acc[16];
                #pragma unroll
                for (int jj = 0; jj < 16; jj++) acc[jj] = 0.f;
                for (int k = 0; k < 128; k++) {
                    float a = __bfloat162float(d_Xh[(size_t)row * 128 + k])
                            + __bfloat162float(d_Xl[(size_t)row * 128 + k]);
                    #pragma unroll
                    for (int jj = 0; jj < 16; jj++) acc[jj] += a * Ws[k * 128 + c0 + jj];
                }
                #pragma unroll
                for (int jj = 0; jj < 16; jj++)
                    d_XWh[(size_t)row * 128 + c0 + jj] = __float2half_rn(acc[jj]);
            }
        }
    }
#endif
}

// ------- fused gather(fp16 XW) + self-loop + bias + leaky + residual (+pool) -------
__global__ void k_gather(const float* __restrict__ bias, int n, int last) {
    int warp = (blockIdx.x * blockDim.x + threadIdx.x) >> 5;
    int lane = threadIdx.x & 31;
    if (warp >= n) return;
    int cnt = d_degi[warp];
    int start = d_offs[warp];
    float di = d_dinv[warp];
    const uint2* xw2 = (const uint2*)d_XWh;   // 4 halves per uint2; row stride 32

    // self loop
    uint2 sp = xw2[(size_t)warp * 32 + lane];
    float2 sa = __half22float2(*(__half2*)&sp.x);
    float2 sb = __half22float2(*(__half2*)&sp.y);
    float ns = di * di;
    float4 acc = make_float4(sa.x * ns, sa.y * ns, sb.x * ns, sb.y * ns);

    int j = 0;
    for (; j + 8 <= cnt; j += 8) {
        uint2 e[8], v[8];
        #pragma unroll
        for (int k = 0; k < 8; k++) e[k] = __ldg(d_edge + start + j + k);
        #pragma unroll
        for (int k = 0; k < 8; k++) v[k] = __ldg(xw2 + (size_t)e[k].x * 32 + lane);
        #pragma unroll
        for (int k = 0; k < 8; k++) {
            float nw = __uint_as_float(e[k].y);
            float2 a = __half22float2(*(__half2*)&v[k].x);
            float2 b = __half22float2(*(__half2*)&v[k].y);
            acc.x += nw * a.x;
            acc.y += nw * a.y;
            acc.z += nw * b.x;
            acc.w += nw * b.y;
        }
    }
    for (; j < cnt; j++) {
        uint2 e0 = __ldg(d_edge + start + j);
        uint2 v0 = __ldg(xw2 + (size_t)e0.x * 32 + lane);
        float n0 = __uint_as_float(e0.y);
        float2 a0 = __half22float2(*(__half2*)&v0.x), b0 = __half22float2(*(__half2*)&v0.y);
        acc.x += n0 * a0.x;
        acc.y += n0 * a0.y;
        acc.z += n0 * b0.x;
        acc.w += n0 * b0.y;
    }

    float4 bv = ((const float4*)bias)[lane];
    acc.x = leaky(acc.x + bv.x);
    acc.y = leaky(acc.y + bv.y);
    acc.z = leaky(acc.z + bv.z);
    acc.w = leaky(acc.w + bv.w);

    // residual from bf16 hi/lo pair — streaming loads (protect XWh L2 residency)
    uint2 xh = __ldcs(((const uint2*)d_Xh) + (size_t)warp * 32 + lane);
    uint2 xl = __ldcs(((const uint2*)d_Xl) + (size_t)warp * 32 + lane);
    __nv_bfloat162 h01 = *(__nv_bfloat162*)&xh.x, h23 = *(__nv_bfloat162*)&xh.y;
    __nv_bfloat162 l01 = *(__nv_bfloat162*)&xl.x, l23 = *(__nv_bfloat162*)&xl.y;
    float4 nx;
    nx.x = __bfloat162float(h01.x) + __bfloat162float(l01.x) + acc.x;
    nx.y = __bfloat162float(h01.y) + __bfloat162float(l01.y) + acc.y;
    nx.z = __bfloat162float(h23.x) + __bfloat162float(l23.x) + acc.z;
    nx.w = __bfloat162float(h23.y) + __bfloat162float(l23.y) + acc.w;

    if (last) {
        // fused mean-pool: sum across 128 channels -> /128
        float s = nx.x + nx.y + nx.z + nx.w;
        #pragma unroll
        for (int off = 16; off > 0; off >>= 1) s += __shfl_down_sync(0xffffffffu, s, off);
        if (lane == 0) d_pooled[warp] = s * (1.f / (float)HC_);
    } else {
        __nv_bfloat16 h0, h1, h2, h3, l0, l1, l2, l3;
        bsplit(nx.x, h0, l0); bsplit(nx.y, h1, l1);
        bsplit(nx.z, h2, l2); bsplit(nx.w, h3, l3);
        uint2 hp, lp;
        hp.x = (uint32_t)__bfloat16_as_ushort(h0) | ((uint32_t)__bfloat16_as_ushort(h1) << 16);
        hp.y = (uint32_t)__bfloat16_as_ushort(h2) | ((uint32_t)__bfloat16_as_ushort(h3) << 16);
        lp.x = (uint32_t)__bfloat16_as_ushort(l0) | ((uint32_t)__bfloat16_as_ushort(l1) << 16);
        lp.y = (uint32_t)__bfloat16_as_ushort(l2) | ((uint32_t)__bfloat16_as_ushort(l3) << 16);
        __stcs(((uint2*)d_Xh) + (size_t)warp * 32 + lane, hp);
        __stcs(((uint2*)d_Xl) + (size_t)warp * 32 + lane, lp);
    }
}

// ---------------- readout ----------------
__global__ void k_final(const float* __restrict__ lw, const float* __restrict__ lb,
                        float* __restrict__ out) {
    __shared__ float sh[128 * NO_];
    int b = blockIdx.x, t = threadIdx.x;
    float acc[NO_];
    #pragma unroll
    for (int j = 0; j < NO_; j++) acc[j] = 0.f;
    for (int tt = t; tt < S_ + R_; tt += 128) {
        float p = d_pooled[b * (S_ + R_) + tt];
        #pragma unroll
        for (int j = 0; j < NO_; j++) acc[j] += p * __ldg(lw + tt * NO_ + j);
    }
    #pragma unroll
    for (int j = 0; j < NO_; j++) sh[t * NO_ + j] = acc[j];
    __syncthreads();
    for (int off = 64; off > 0; off >>= 1) {
        if (t < off) {
            #pragma unroll
            for (int j = 0; j < NO_; j++) sh[t * NO_ + j] += sh[(t + off) * NO_ + j];
        }
        __syncthreads();
    }
    if (t == 0) {
        float z[NO_], sum = 0.f;
        #pragma unroll
        for (int j = 0; j < NO_; j++) { z[j] = expf(sh[j] + lb[j]); sum += z[j]; }
        float inv = 1.f / (sum + 1.f);
        #pragma unroll
        for (int j = 0; j < NO_; j++)
            out[b * NO_ + j] = z[j] * inv * expf(d_O[b * NO_ + j]);
    }
}

// ---------------- host orchestration ----------------
extern "C" void kernel_launch(void* const* d_in, const int* in_sizes, int n_in,
                              void* d_out, int out_size) {
    const float* s_x     = (const float*)d_in[0];
    const float* r_x     = (const float*)d_in[1];
    const int*   ei      = (const int*)d_in[2];
    const float* bn_s_w  = (const float*)d_in[3];
    const float* bn_s_b  = (const float*)d_in[4];
    const float* bn_r_w  = (const float*)d_in[5];
    const float* bn_r_b  = (const float*)d_in[6];
    const float* lin_s_w = (const float*)d_in[7];
    const float* lin_r_w = (const float*)d_in[8];
    const float* conv_w  = (const float*)d_in[9];
    const float* conv_b  = (const float*)d_in[10];
    const float* linr_w  = (const float*)d_in[11];
    const float* linr_b  = (const float*)d_in[12];
    const float* lino_w1 = (const float*)d_in[13];
    const float* lino_b1 = (const float*)d_in[14];
    const float* lino_w2 = (const float*)d_in[15];
    const float* lino_b2 = (const float*)d_in[16];
    float* out = (float*)d_out;

    int E  = in_sizes[2] / 2;
    int Bn = in_sizes[1] / (R_ * (RC_ + 5));
    int n  = Bn * (S_ + R_);
    int rowsS = Bn * S_, rowsR = Bn * R_;
    const int* src = ei;
    const int* dst = ei + E;

    static const int MMA_SMEM = 6 * 32768 + 1024;   // 193 KB (1 CTA/SM, persistent)
    cudaFuncSetAttribute(k_mma, cudaFuncAttributeMaxDynamicSharedMemorySize, MMA_SMEM);

    // encoder chain first (d_stats starts zero: static init + k_prep re-zeroes)
    k_stats_s<<<96, 256>>>(s_x, rowsS);                                      // 1
    k_stats_r<<<192, 256>>>(r_x, rowsR);                                     // 2
    k_prep<<<1, 32>>>(bn_s_w, bn_s_b, bn_r_w, bn_r_b, rowsS, rowsR);         // 3
    k_featO<<<n + Bn, 128>>>(s_x, r_x, lin_s_w, lin_r_w,                     // 4
                             lino_w1, lino_b1, lino_w2, lino_b2, n);
    k_wsplit<<<L_, 256>>>(conv_w);                                           // 5
    k_mma<<<148, 128, MMA_SMEM>>>(conv_w, 0, n);                             // 6 (layer 0)

    // CSR build (only needed before first gather)
    k_zero<<<(n + 255) / 256, 256>>>(n);                                     // 7
    k_count<<<(E + 255) / 256, 256>>>(dst, E);                               // 8
    int nb1 = (n + 511) / 512;
    k_scan1<<<nb1, 512>>>(n);                                                // 9 (+dinv)
    k_scan2<<<1, 512>>>(nb1);                                                // 10
    k_scan3<<<(n + 255) / 256, 256>>>(n);                                    // 11
    k_fill<<<(E + 255) / 256, 256>>>(src, dst, E);                           // 12

    // layers
    int gather_blocks = (n * 32 + 255) / 256;
    k_gather<<<gather_blocks, 256>>>(conv_b, n, 0);                          // 13
    for (int l = 1; l < L_; l++) {
        k_mma<<<148, 128, MMA_SMEM>>>(conv_w + (size_t)l * HC_ * HC_, l, n);
        k_gather<<<gather_blocks, 256>>>(conv_b + l * HC_, n, l == L_ - 1);
    }

    // readout (pool fused into last gather)
    k_final<<<Bn, 128>>>(linr_w, linr_b, out);
}

// round 12
// speedup vs baseline: 1.1455x; 1.1455x over previous
#include <cuda_runtime.h>
#include <cuda_bf16.h>
#include <cuda_fp16.h>
#include <cstdint>

#define S_   38
#define R_   340
#define HC_  128
#define SC_  4
#define RC_  3
#define NO_  7
#define L_   4
#define BMAX 512
#define NMAX (BMAX * (S_ + R_))   // 193536
#define EMAX 3072000

// ---------------- scratch (device globals; no allocation allowed) ----------------
__device__ __nv_bfloat16 d_Xh[NMAX * HC_];      // X split hi (49.5 MB) — residual hi
__device__ __nv_bfloat16 d_Xl[NMAX * HC_];      // X split lo (49.5 MB) — residual lo
__device__ __half        d_XWh[NMAX * HC_];     // X @ W in fp16 (49.5 MB, L2-resident)
__device__ int   d_degi[NMAX];
__device__ float d_dinv[NMAX];
__device__ int   d_offs[NMAX];
__device__ int   d_curs[NMAX];
__device__ int   d_bsum[512];
__device__ uint2 d_edge[EMAX];                  // packed (src, norm-bits) per CSR slot
__device__ float d_stats[16];                   // zero-init; re-zeroed by k_prep each call
__device__ float d_pre[16];
__device__ float d_O[BMAX * NO_];
__device__ float d_pooled[NMAX];
// pre-split weights in blocked-swizzled MMA layout (bf16 hi/lo), 32 KB per layer each
__device__ __align__(16) unsigned char d_Wh[L_][32768];
__device__ __align__(16) unsigned char d_Wl[L_][32768];

__device__ __forceinline__ float leaky(float x) { return x > 0.f ? x : 0.2f * x; }

// ================= tcgen05 helpers (verified rounds 5/8/9/10) =============
__device__ __forceinline__ uint32_t smem_u32(const void* p) {
    uint32_t a;
    asm("{ .reg .u64 t; cvta.to.shared.u64 t, %1; cvt.u32.u64 %0, t; }" : "=r"(a) : "l"(p));
    return a;
}
__device__ __forceinline__ uint32_t elect_one() {
    uint32_t pred;
    asm volatile("{\n\t.reg .pred p;\n\telect.sync _|p, 0xFFFFFFFF;\n\tselp.b32 %0, 1, 0, p;\n\t}" : "=r"(pred));
    return pred;
}
#define TCG_ALLOC(dst_smem, n) \
    asm volatile("tcgen05.alloc.cta_group::1.sync.aligned.shared::cta.b32 [%0], %1;" \
                 :: "r"(dst_smem), "r"((uint32_t)(n)) : "memory")
#define TCG_DEALLOC(tmem, n) \
    asm volatile("tcgen05.dealloc.cta_group::1.sync.aligned.b32 %0, %1;" :: "r"(tmem), "r"((uint32_t)(n)))
#define TCG_RELINQ() asm volatile("tcgen05.relinquish_alloc_permit.cta_group::1.sync.aligned;")
#define TCG_COMMIT(mbar) \
    asm volatile("tcgen05.commit.cta_group::1.mbarrier::arrive::one.shared::cluster.b64 [%0];" \
                 :: "r"(mbar) : "memory")
#define TCG_FENCE_BEFORE() asm volatile("tcgen05.fence::before_thread_sync;" ::: "memory")
#define TCG_FENCE_AFTER()  asm volatile("tcgen05.fence::after_thread_sync;" ::: "memory")
#define TCG_WAIT_LD() asm volatile("tcgen05.wait::ld.sync.aligned;" ::: "memory")
#define FENCE_ASYNC_SHARED() asm volatile("fence.proxy.async.shared::cta;" ::: "memory")
#define MBAR_INIT(mbar, cnt) \
    asm volatile("mbarrier.init.shared.b64 [%0], %1;" :: "r"(mbar), "r"((uint32_t)(cnt)) : "memory")
#define MBAR_INVAL(mbar) asm volatile("mbarrier.inval.shared.b64 [%0];" :: "r"(mbar) : "memory")

__device__ __forceinline__ void mbar_wait_parity(uint32_t mbar, uint32_t parity) {
    uint32_t done;
    asm volatile("{\n\t.reg .pred p;\n\t"
                 "mbarrier.try_wait.parity.acquire.cta.shared::cta.b64 p, [%1], %2;\n\t"
                 "selp.b32 %0, 1, 0, p;\n\t}"
                 : "=r"(done) : "r"(mbar), "r"(parity) : "memory");
    if (!done) {
        asm volatile("{\n\t.reg .pred P1;\n\t"
                     "WL_%=:\n\t"
                     "mbarrier.try_wait.parity.acquire.cta.shared::cta.b64 P1, [%0], %1, 0x989680;\n\t"
                     "@P1 bra.uni WD_%=;\n\t"
                     "bra.uni WL_%=;\n\t"
                     "WD_%=:\n\t}"
                     :: "r"(mbar), "r"(parity) : "memory");
    }
}

#define TCG_LD_32X32B_X32(r, tmem) \
    asm volatile( \
        "tcgen05.ld.sync.aligned.32x32b.x32.b32 " \
        "{%0, %1, %2, %3, %4, %5, %6, %7, " \
        " %8, %9, %10, %11, %12, %13, %14, %15, " \
        " %16, %17, %18, %19, %20, %21, %22, %23, " \
        " %24, %25, %26, %27, %28, %29, %30, %31}, [%32];" \
        : "=r"((r)[0]),  "=r"((r)[1]),  "=r"((r)[2]),  "=r"((r)[3]), \
          "=r"((r)[4]),  "=r"((r)[5]),  "=r"((r)[6]),  "=r"((r)[7]), \
          "=r"((r)[8]),  "=r"((r)[9]),  "=r"((r)[10]), "=r"((r)[11]), \
          "=r"((r)[12]), "=r"((r)[13]), "=r"((r)[14]), "=r"((r)[15]), \
          "=r"((r)[16]), "=r"((r)[17]), "=r"((r)[18]), "=r"((r)[19]), \
          "=r"((r)[20]), "=r"((r)[21]), "=r"((r)[22]), "=r"((r)[23]), \
          "=r"((r)[24]), "=r"((r)[25]), "=r"((r)[26]), "=r"((r)[27]), \
          "=r"((r)[28]), "=r"((r)[29]), "=r"((r)[30]), "=r"((r)[31]) \
        : "r"(tmem))

// SW128 K-major SMEM descriptor (layout=2, version=1, SBO=64, LBO=1)
static __device__ __forceinline__ uint64_t make_desc(uint32_t addr) {
    return ((uint64_t)2 << 61) | ((uint64_t)1 << 46) | ((uint64_t)64 << 32)
         | ((uint64_t)1 << 16) | (uint64_t)((addr >> 4) & 0x3FFF);
}
__device__ __forceinline__ uint32_t sw128(uint32_t off) { return off ^ ((off >> 3) & 0x70); }

// blocked-atom byte offset for bf16 K-major tile, 128 rows x 128 K-cols
__device__ __forceinline__ uint32_t bf16_off(int row, int col) {
    uint32_t off = (uint32_t)(((row >> 3) + (col >> 6) * 16) * 1024 + (row & 7) * 128 + (col & 63) * 2);
    return sw128(off);
}

#if defined(__CUDA_ARCH_FEAT_SM103_ALL) || !defined(__CUDA_ARCH__)
__device__ __forceinline__ void mma_f16_ss(uint32_t d, uint64_t ad, uint64_t bd,
                                           uint32_t idesc, bool acc) {
    uint32_t en = acc ? 1u : 0u;
    asm volatile(
        "{\n\t.reg .pred p;\n\tsetp.ne.u32 p, %5, 0;\n\t"
        "tcgen05.mma.cta_group::1.kind::f16 [%0], %1, %2, %3, {%4, %4, %4, %4}, p;\n\t}"
        :: "r"(d), "l"(ad), "l"(bd), "r"(idesc), "r"(0u), "r"(en) : "memory");
}
#endif

// idesc: dtype=F32, atype=BF16, btype=BF16, N=128, M=128
#define MMA_IDESC ((1u << 4) | (1u << 7) | (1u << 10) | (16u << 17) | (8u << 24))

// split helper: fp32 -> (hi, lo) bf16
__device__ __forceinline__ void bsplit(float v, __nv_bfloat16& h, __nv_bfloat16& l) {
    h = __float2bfloat16_rn(v);
    l = __float2bfloat16_rn(v - __bfloat162float(h));
}

// ---------------- batchnorm stats (d_stats zeroed by k_prep / static init) --------
__global__ void k_stats_s(const float* __restrict__ sx, int rows) {
    const float4* v4 = (const float4*)sx;
    float s0 = 0, s1 = 0, s2 = 0, s3 = 0, q0 = 0, q1 = 0, q2 = 0, q3 = 0;
    for (int r = blockIdx.x * blockDim.x + threadIdx.x; r < rows; r += gridDim.x * blockDim.x) {
        float4 v = v4[r];
        s0 += v.x; q0 += v.x * v.x;
        s1 += v.y; q1 += v.y * v.y;
        s2 += v.z; q2 += v.z * v.z;
        s3 += v.w; q3 += v.w * v.w;
    }
    #pragma unroll
    for (int off = 16; off > 0; off >>= 1) {
        s0 += __shfl_down_sync(0xffffffffu, s0, off);
        s1 += __shfl_down_sync(0xffffffffu, s1, off);
        s2 += __shfl_down_sync(0xffffffffu, s2, off);
        s3 += __shfl_down_sync(0xffffffffu, s3, off);
        q0 += __shfl_down_sync(0xffffffffu, q0, off);
        q1 += __shfl_down_sync(0xffffffffu, q1, off);
        q2 += __shfl_down_sync(0xffffffffu, q2, off);
        q3 += __shfl_down_sync(0xffffffffu, q3, off);
    }
    if ((threadIdx.x & 31) == 0) {
        atomicAdd(&d_stats[0], s0); atomicAdd(&d_stats[1], s1);
        atomicAdd(&d_stats[2], s2); atomicAdd(&d_stats[3], s3);
        atomicAdd(&d_stats[4], q0); atomicAdd(&d_stats[5], q1);
        atomicAdd(&d_stats[6], q2); atomicAdd(&d_stats[7], q3);
    }
}

__global__ void k_stats_r(const float* __restrict__ rx, int rows) {
    const float4* v4 = (const float4*)rx;
    float s0 = 0, s1 = 0, s2 = 0, q0 = 0, q1 = 0, q2 = 0;
    for (int r = blockIdx.x * blockDim.x + threadIdx.x; r < rows; r += gridDim.x * blockDim.x) {
        float4 v = v4[r * 2];
        s0 += v.x; q0 += v.x * v.x;
        s1 += v.y; q1 += v.y * v.y;
        s2 += v.z; q2 += v.z * v.z;
    }
    #pragma unroll
    for (int off = 16; off > 0; off >>= 1) {
        s0 += __shfl_down_sync(0xffffffffu, s0, off);
        s1 += __shfl_down_sync(0xffffffffu, s1, off);
        s2 += __shfl_down_sync(0xffffffffu, s2, off);
        q0 += __shfl_down_sync(0xffffffffu, q0, off);
        q1 += __shfl_down_sync(0xffffffffu, q1, off);
        q2 += __shfl_down_sync(0xffffffffu, q2, off);
    }
    if ((threadIdx.x & 31) == 0) {
        atomicAdd(&d_stats[8],  s0); atomicAdd(&d_stats[9],  s1);
        atomicAdd(&d_stats[10], s2); atomicAdd(&d_stats[11], q0);
        atomicAdd(&d_stats[12], q1); atomicAdd(&d_stats[13], q2);
    }
}

// computes bn scale/shift, then re-zeroes d_stats for the next graph replay
__global__ void k_prep(const float* __restrict__ bsw, const float* __restrict__ bsb,
                       const float* __restrict__ brw, const float* __restrict__ brb,
                       int ns, int nr) {
    int t = threadIdx.x;
    if (t < 4) {
        float m = d_stats[t] / (float)ns;
        float var = d_stats[4 + t] / (float)ns - m * m;
        float sc = rsqrtf(var + 1e-5f) * bsw[t];
        d_pre[t] = sc;
        d_pre[4 + t] = bsb[t] - m * sc;
    } else if (t < 7) {
        int c = t - 4;
        float m = d_stats[8 + c] / (float)nr;
        float var = d_stats[11 + c] / (float)nr - m * m;
        float sc = rsqrtf(var + 1e-5f) * brw[c];
        d_pre[8 + c] = sc;
        d_pre[11 + c] = brb[c] - m * sc;
    }
    __syncthreads();
    if (t < 16) d_stats[t] = 0.f;
}

// -------- feature encoder (warp-per-node, bn folded into smem weights) + o-branch --
// blocks [0, nbF): 8 nodes each (one per warp). blocks [nbF, nbF+Bn): o-branch.
__global__ void __launch_bounds__(256) k_featO(
        const float* __restrict__ sx, const float* __restrict__ rx,
        const float* __restrict__ wsl, const float* __restrict__ wrl,
        const float* __restrict__ w1, const float* __restrict__ b1,
        const float* __restrict__ w2, const float* __restrict__ b2,
        int n, int nbF) {
    int tid = threadIdx.x;
    if ((int)blockIdx.x < nbF) {
        __shared__ float ws[SC_ * HC_];   // scaled s-weights
        __shared__ float wr[RC_ * HC_];   // scaled r-weights
        __shared__ float bs[HC_], br[HC_];
        for (int i = tid; i < SC_ * HC_; i += 256)
            ws[i] = __ldg(wsl + i) * d_pre[i >> 7];
        for (int i = tid; i < RC_ * HC_; i += 256)
            wr[i] = __ldg(wrl + i) * d_pre[8 + (i >> 7)];
        if (tid < HC_) {
            float as = 0.f, ar = 0.f;
            #pragma unroll
            for (int c = 0; c < SC_; c++) as += d_pre[4 + c] * __ldg(wsl + c * HC_ + tid);
            #pragma unroll
            for (int c = 0; c < RC_; c++) ar += d_pre[11 + c] * __ldg(wrl + c * HC_ + tid);
            bs[tid] = as;
            br[tid] = ar;
        }
        __syncthreads();
        int wid = tid >> 5, lane = tid & 31;
        int node = blockIdx.x * 8 + wid;
        if (node >= n) return;
        int b = node / (S_ + R_);
        int pos = node - b * (S_ + R_);
        float4 xv = make_float4(0.f, 0.f, 0.f, 0.f);
        if (lane == 0) {
            if (pos < S_) xv = ((const float4*)sx)[b * S_ + pos];
            else          xv = ((const float4*)rx)[(size_t)(b * R_ + pos - S_) * 2];
        }
        float x0 = __shfl_sync(0xffffffffu, xv.x, 0);
        float x1 = __shfl_sync(0xffffffffu, xv.y, 0);
        float x2 = __shfl_sync(0xffffffffu, xv.z, 0);
        float x3 = __shfl_sync(0xffffffffu, xv.w, 0);
        float4 a;
        if (pos < S_) {
            float4 w0 = ((float4*)ws)[lane];
            float4 w1v = ((float4*)ws)[32 + lane];
            float4 w2v = ((float4*)ws)[64 + lane];
            float4 w3v = ((float4*)ws)[96 + lane];
            float4 bb = ((float4*)bs)[lane];
            a.x = bb.x + x0 * w0.x + x1 * w1v.x + x2 * w2v.x + x3 * w3v.x;
            a.y = bb.y + x0 * w0.y + x1 * w1v.y + x2 * w2v.y + x3 * w3v.y;
            a.z = bb.z + x0 * w0.z + x1 * w1v.z + x2 * w2v.z + x3 * w3v.z;
            a.w = bb.w + x0 * w0.w + x1 * w1v.w + x2 * w2v.w + x3 * w3v.w;
        } else {
            float4 w0 = ((float4*)wr)[lane];
            float4 w1v = ((float4*)wr)[32 + lane];
            float4 w2v = ((float4*)wr)[64 + lane];
            float4 bb = ((float4*)br)[lane];
            a.x = bb.x + x0 * w0.x + x1 * w1v.x + x2 * w2v.x;
            a.y = bb.y + x0 * w0.y + x1 * w1v.y + x2 * w2v.y;
            a.z = bb.z + x0 * w0.z + x1 * w1v.z + x2 * w2v.z;
            a.w = bb.w + x0 * w0.w + x1 * w1v.w + x2 * w2v.w;
        }
        a.x = leaky(a.x); a.y = leaky(a.y); a.z = leaky(a.z); a.w = leaky(a.w);
        __nv_bfloat16 h0, h1, h2, h3, l0, l1, l2, l3;
        bsplit(a.x, h0, l0); bsplit(a.y, h1, l1);
        bsplit(a.z, h2, l2); bsplit(a.w, h3, l3);
        uint2 hp, lp;
        hp.x = (uint32_t)__bfloat16_as_ushort(h0) | ((uint32_t)__bfloat16_as_ushort(h1) << 16);
        hp.y = (uint32_t)__bfloat16_as_ushort(h2) | ((uint32_t)__bfloat16_as_ushort(h3) << 16);
        lp.x = (uint32_t)__bfloat16_as_ushort(l0) | ((uint32_t)__bfloat16_as_ushort(l1) << 16);
        lp.y = (uint32_t)__bfloat16_as_ushort(l2) | ((uint32_t)__bfloat16_as_ushort(l3) << 16);
        ((uint2*)d_Xh)[(size_t)node * 32 + lane] = hp;
        ((uint2*)d_Xl)[(size_t)node * 32 + lane] = lp;
    } else {
        __shared__ float sh[HC_];
        int b = blockIdx.x - nbF;
        int h = tid;
        if (h < HC_) {
            float acc = b1[h];
            #pragma unroll
            for (int c = 0; c < 5; c++)
                acc += __ldg(rx + (size_t)(b * R_) * (RC_ + 5) + RC_ + c) * __ldg(w1 + c * HC_ + h);
            sh[h] = leaky(acc);
        }
        __syncthreads();
        if (h < NO_) {
            float o = b2[h];
            #pragma unroll 8
            for (int k = 0; k < HC_; k++) o += sh[k] * __ldg(w2 + k * NO_ + h);
            d_O[b * NO_ + h] = o;
        }
    }
}

// ---------------- W split precompute (once; all layers) ----------------
__global__ void k_wsplit(const float* __restrict__ conv_w) {
    int l = blockIdx.x;
    const float* W = conv_w + (size_t)l * HC_ * HC_;
    for (int i = threadIdx.x; i < HC_ * HC_; i += blockDim.x) {
        int k = i >> 7, nn = i & 127;
        float v = __ldg(W + k * 128 + nn);
        __nv_bfloat16 h, lo;
        bsplit(v, h, lo);
        uint32_t off = bf16_off(nn, k);   // B[n][k] = W[k][n]
        *(__nv_bfloat16*)(d_Wh[l] + off) = h;
        *(__nv_bfloat16*)(d_Wl[l] + off) = lo;
    }
}

// ---------------- init / degree / CSR ----------------
__global__ void k_zero(int n) {
    int i = blockIdx.x * blockDim.x + threadIdx.x;
    if (i < n) d_degi[i] = 0;
}

__global__ void k_count(const int* __restrict__ dst, int E) {
    int e = blockIdx.x * blockDim.x + threadIdx.x;
    if (e < E) atomicAdd(&d_degi[dst[e]], 1);
}

// scan1 also emits dinv (folded former k_dinv pass)
__global__ void k_scan1(int n) {
    __shared__ int sh[512];
    int t = threadIdx.x;
    int g = blockIdx.x * 512 + t;
    int v = (g < n) ? d_degi[g] : 0;
    if (g < n) d_dinv[g] = rsqrtf((float)(v + 1));
    sh[t] = v;
    __syncthreads();
    #pragma unroll
    for (int off = 1; off < 512; off <<= 1) {
        int a = sh[t];
        int b = (t >= off) ? sh[t - off] : 0;
        __syncthreads();
        sh[t] = a + b;
        __syncthreads();
    }
    if (g < n) d_offs[g] = sh[t] - v;
    if (t == 511) d_bsum[blockIdx.x] = sh[511];
}

__global__ void k_scan2(int nb) {
    __shared__ int sh[512];
    int t = threadIdx.x;
    int v = (t < nb) ? d_bsum[t] : 0;
    sh[t] = v;
    __syncthreads();
    #pragma unroll
    for (int off = 1; off < 512; off <<= 1) {
        int a = sh[t];
        int b = (t >= off) ? sh[t - off] : 0;
        __syncthreads();
        sh[t] = a + b;
        __syncthreads();
    }
    if (t < nb) d_bsum[t] = sh[t] - v;
}

__global__ void k_scan3(int n) {
    int g = blockIdx.x * blockDim.x + threadIdx.x;
    if (g < n) {
        int o = d_offs[g] + d_bsum[g >> 9];
        d_offs[g] = o;
        d_curs[g] = o;
    }
}

__global__ void k_fill(const int* __restrict__ src, const int* __restrict__ dst, int E) {
    int e = blockIdx.x * blockDim.x + threadIdx.x;
    if (e < E) {
        int s = src[e], d = dst[e];
        int p = atomicAdd(&d_curs[d], 1);
        float nw = d_dinv[s] * d_dinv[d];
        d_edge[p] = make_uint2((uint32_t)s, __float_as_uint(nw));
    }
}

// =============== persistent pipelined tcgen05 bf16x3 GEMM: XWh = fp16(X @ W) ======
__global__ void __launch_bounds__(128) k_mma(const float* __restrict__ W, int layer, int n) {
    extern __shared__ char dyn_smem[];
#if defined(__CUDA_ARCH_FEAT_SM103_ALL) || !defined(__CUDA_ARCH__)
    __shared__ uint32_t s_tmem[2];
    __shared__ __align__(8) unsigned long long s_mbar[2];

    char* base = (char*)(((uintptr_t)dyn_smem + 1023) & ~(uintptr_t)1023);
    char* A0h = base;
    char* A0l = base + 32768;
    char* A1h = base + 65536;
    char* A1l = base + 98304;
    char* Bh  = base + 131072;
    char* Bl  = base + 163840;   // total 192 KB

    int tid = threadIdx.x, wid = tid >> 5, lane = tid & 31;

    if (wid == 0) TCG_ALLOC(smem_u32(s_tmem), 256);
    if (tid == 0) {
        MBAR_INIT(smem_u32(&s_mbar[0]), 1);
        MBAR_INIT(smem_u32(&s_mbar[1]), 1);
    }
    __syncthreads();
    uint32_t tmem;
    asm volatile("ld.shared.b32 %0, [%1];" : "=r"(tmem) : "r"(smem_u32(s_tmem)));

    // stage pre-split W (coalesced uint4 copy, once per CTA)
    {
        const uint4* gh = (const uint4*)d_Wh[layer];
        const uint4* gl = (const uint4*)d_Wl[layer];
        uint4* sh = (uint4*)Bh;
        uint4* sl = (uint4*)Bl;
        for (int i = tid; i < 2048; i += 128) { sh[i] = gh[i]; sl[i] = gl[i]; }
    }

    const uint64_t bdh = make_desc(smem_u32(Bh));
    const uint64_t bdl = make_desc(smem_u32(Bl));
    const uint4* GXh = (const uint4*)d_Xh;   // row = 16 uint4 (128 bf16)
    const uint4* GXl = (const uint4*)d_Xl;
    __half* XWh = d_XWh;

    int tiles = (n + 127) >> 7;
    uint32_t ph0 = 0, ph1 = 0;
    int j = 0, prev_t = -1;

    for (int t = blockIdx.x; t < tiles; t += gridDim.x, j++) {
        int buf = j & 1;
        char* Ah = buf ? A1h : A0h;
        char* Al = buf ? A1l : A0l;
        int row0 = t << 7;

        // --- stage A tile: swizzled uint4 copy (overlaps in-flight MMA[j-1]) ---
        #pragma unroll 4
        for (int i = tid; i < 2048; i += 128) {          // 128 rows x 16 quads
            int row = i >> 4, q = i & 15;
            uint4 vh = make_uint4(0u, 0u, 0u, 0u), vl = vh;
            if (row0 + row < n) {
                size_t gi = (size_t)(row0 + row) * 16 + q;
                vh = __ldg(GXh + gi);
                vl = __ldg(GXl + gi);
            }
            uint32_t off = bf16_off(row, q * 8);
            *(uint4*)(Ah + off) = vh;
            *(uint4*)(Al + off) = vl;
        }
        TCG_FENCE_BEFORE();
        __syncthreads();

        // --- wait for MMA[j-1] ---
        if (j > 0) {
            if (buf) { mbar_wait_parity(smem_u32(&s_mbar[0]), ph0); ph0 ^= 1; }
            else     { mbar_wait_parity(smem_u32(&s_mbar[1]), ph1); ph1 ^= 1; }
            TCG_FENCE_AFTER();
        }

        // --- issue MMA[j] ---
        if (wid == 0) {
            TCG_FENCE_AFTER();
            if (elect_one()) {
                FENCE_ASYNC_SHARED();
                uint64_t adh = make_desc(smem_u32(Ah));
                uint64_t adl = make_desc(smem_u32(Al));
                uint32_t D = tmem + buf * 128;
                #pragma unroll
                for (int s = 0; s < 8; s++) {
                    uint64_t off = (uint64_t)((s & 3) * 2 + (s >> 2) * 1024);
                    mma_f16_ss(D, adh + off, bdh + off, MMA_IDESC, s > 0);
                }
                #pragma unroll
                for (int s = 0; s < 8; s++) {
                    uint64_t off = (uint64_t)((s & 3) * 2 + (s >> 2) * 1024);
                    mma_f16_ss(D, adl + off, bdh + off, MMA_IDESC, true);
                }
                #pragma unroll
                for (int s = 0; s < 8; s++) {
                    uint64_t off = (uint64_t)((s & 3) * 2 + (s >> 2) * 1024);
                    mma_f16_ss(D, adh + off, bdl + off, MMA_IDESC, true);
                }
                TCG_COMMIT(smem_u32(&s_mbar[buf]));
            }
        }

        // --- epilogue for tile j-1 (overlaps MMA[j]); fp16 output ---
        if (j > 0) {
            int prow = (prev_t << 7) + wid * 32 + lane;
            uint32_t Dp = tmem + (1 - buf) * 128;
            uint32_t r[32];
            #pragma unroll
            for (int c0 = 0; c0 < 128; c0 += 32) {
                TCG_LD_32X32B_X32(r, Dp + c0);
                TCG_WAIT_LD();
                if (prow < n) {
                    uint32_t h2[16];
                    #pragma unroll
                    for (int k = 0; k < 16; k++) {
                        __half2 p = __floats2half2_rn(__uint_as_float(r[2 * k]),
                                                      __uint_as_float(r[2 * k + 1]));
                        h2[k] = *(uint32_t*)&p;
                    }
                    uint4* dst = (uint4*)(XWh + (size_t)prow * 128 + c0);
                    dst[0] = make_uint4(h2[0], h2[1], h2[2], h2[3]);
                    dst[1] = make_uint4(h2[4], h2[5], h2[6], h2[7]);
                    dst[2] = make_uint4(h2[8], h2[9], h2[10], h2[11]);
                    dst[3] = make_uint4(h2[12], h2[13], h2[14], h2[15]);
                }
            }
            TCG_FENCE_BEFORE();
        }
        prev_t = t;
    }

    // --- drain last tile ---
    if (j > 0) {
        int buf = (j - 1) & 1;
        if (buf) { mbar_wait_parity(smem_u32(&s_mbar[1]), ph1); ph1 ^= 1; }
        else     { mbar_wait_parity(smem_u32(&s_mbar[0]), ph0); ph0 ^= 1; }
        TCG_FENCE_AFTER();
        int prow = (prev_t << 7) + wid * 32 + lane;
        uint32_t Dp = tmem + buf * 128;
        uint32_t r[32];
        #pragma unroll
        for (int c0 = 0; c0 < 128; c0 += 32) {
            TCG_LD_32X32B_X32(r, Dp + c0);
            TCG_WAIT_LD();
            if (prow < n) {
                uint32_t h2[16];
                #pragma unroll
                for (int k = 0; k < 16; k++) {
                    __half2 p = __floats2half2_rn(__uint_as_float(r[2 * k]),
                                                  __uint_as_float(r[2 * k + 1]));
                    h2[k] = *(uint32_t*)&p;
                }
                uint4* dst = (uint4*)(XWh + (size_t)prow * 128 + c0);
                dst[0] = make_uint4(h2[0], h2[1], h2[2], h2[3]);
                dst[1] = make_uint4(h2[4], h2[5], h2[6], h2[7]);
                dst[2] = make_uint4(h2[8], h2[9], h2[10], h2[11]);
                dst[3] = make_uint4(h2[12], h2[13], h2[14], h2[15]);
            }
        }
        TCG_FENCE_BEFORE();
    }
    __syncthreads();
    if (wid == 0) {
        if (elect_one()) {
            MBAR_INVAL(smem_u32(&s_mbar[0]));
            MBAR_INVAL(smem_u32(&s_mbar[1]));
        }
        TCG_RELINQ();
        TCG_DEALLOC(tmem, 256);
    }
#else
    // fp32 fallback for the non-'a' gencode pass (never selected at runtime on GB300)
    float* Ws = (float*)(((uintptr_t)dyn_smem + 1023) & ~(uintptr_t)1023);  // 64 KB
    int tid = threadIdx.x;
    for (int i = tid; i < 128 * 128; i += 128) Ws[i] = __ldg(W + i);
    __syncthreads();
    int tiles = (n + 127) >> 7;
    for (int t = blockIdx.x; t < tiles; t += gridDim.x) {
        int row = (t << 7) + tid;
        if (row < n) {
            for (int c0 = 0; c0 < 128; c0 += 16) {
                float acc[16];
                #pragma unroll
                for (int jj = 0; jj < 16; jj++) acc[jj] = 0.f;
                for (int k = 0; k < 128; k++) {
                    float a = __bfloat162float(d_Xh[(size_t)row * 128 + k])
                            + __bfloat162float(d_Xl[(size_t)row * 128 + k]);
                    #pragma unroll
                    for (int jj = 0; jj < 16; jj++) acc[jj] += a * Ws[k * 128 + c0 + jj];
                }
                #pragma unroll
                for (int jj = 0; jj < 16; jj++)
                    d_XWh[(size_t)row * 128 + c0 + jj] = __float2half_rn(acc[jj]);
            }
        }
    }
#endif
}

// ------- fused gather(fp16 XW) + self-loop + bias + leaky + residual (+pool) -------
__global__ void k_gather(const float* __restrict__ bias, int n, int last) {
    int warp = (blockIdx.x * blockDim.x + threadIdx.x) >> 5;
    int lane = threadIdx.x & 31;
    if (warp >= n) return;
    int cnt = d_degi[warp];
    int start = d_offs[warp];
    float di = d_dinv[warp];
    const uint2* xw2 = (const uint2*)d_XWh;   // 4 halves per uint2; row stride 32

    // self loop
    uint2 sp = xw2[(size_t)warp * 32 + lane];
    float2 sa = __half22float2(*(__half2*)&sp.x);
    float2 sb = __half22float2(*(__half2*)&sp.y);
    float ns = di * di;
    float4 acc = make_float4(sa.x * ns, sa.y * ns, sb.x * ns, sb.y * ns);

    int j = 0;
    for (; j + 4 <= cnt; j += 4) {
        uint2 e0 = __ldg(d_edge + start + j);
        uint2 e1 = __ldg(d_edge + start + j + 1);
        uint2 e2 = __ldg(d_edge + start + j + 2);
        uint2 e3 = __ldg(d_edge + start + j + 3);
        uint2 v0 = __ldg(xw2 + (size_t)e0.x * 32 + lane);
        uint2 v1 = __ldg(xw2 + (size_t)e1.x * 32 + lane);
        uint2 v2 = __ldg(xw2 + (size_t)e2.x * 32 + lane);
        uint2 v3 = __ldg(xw2 + (size_t)e3.x * 32 + lane);
        float n0 = __uint_as_float(e0.y), n1 = __uint_as_float(e1.y);
        float n2 = __uint_as_float(e2.y), n3 = __uint_as_float(e3.y);
        float2 a0 = __half22float2(*(__half2*)&v0.x), b0 = __half22float2(*(__half2*)&v0.y);
        float2 a1 = __half22float2(*(__half2*)&v1.x), b1 = __half22float2(*(__half2*)&v1.y);
        float2 a2 = __half22float2(*(__half2*)&v2.x), b2 = __half22float2(*(__half2*)&v2.y);
        float2 a3 = __half22float2(*(__half2*)&v3.x), b3 = __half22float2(*(__half2*)&v3.y);
        acc.x += n0 * a0.x + n1 * a1.x + n2 * a2.x + n3 * a3.x;
        acc.y += n0 * a0.y + n1 * a1.y + n2 * a2.y + n3 * a3.y;
        acc.z += n0 * b0.x + n1 * b1.x + n2 * b2.x + n3 * b3.x;
        acc.w += n0 * b0.y + n1 * b1.y + n2 * b2.y + n3 * b3.y;
    }
    for (; j < cnt; j++) {
        uint2 e0 = __ldg(d_edge + start + j);
        uint2 v0 = __ldg(xw2 + (size_t)e0.x * 32 + lane);
        float n0 = __uint_as_float(e0.y);
        float2 a0 = __half22float2(*(__half2*)&v0.x), b0 = __half22float2(*(__half2*)&v0.y);
        acc.x += n0 * a0.x;
        acc.y += n0 * a0.y;
        acc.z += n0 * b0.x;
        acc.w += n0 * b0.y;
    }

    float4 bv = ((const float4*)bias)[lane];
    acc.x = leaky(acc.x + bv.x);
    acc.y = leaky(acc.y + bv.y);
    acc.z = leaky(acc.z + bv.z);
    acc.w = leaky(acc.w + bv.w);

    // residual from bf16 hi/lo pair
    uint2 xh = __ldg(((const uint2*)d_Xh) + (size_t)warp * 32 + lane);
    uint2 xl = __ldg(((const uint2*)d_Xl) + (size_t)warp * 32 + lane);
    __nv_bfloat162 h01 = *(__nv_bfloat162*)&xh.x, h23 = *(__nv_bfloat162*)&xh.y;
    __nv_bfloat162 l01 = *(__nv_bfloat162*)&xl.x, l23 = *(__nv_bfloat162*)&xl.y;
    float4 nx;
    nx.x = __bfloat162float(h01.x) + __bfloat162float(l01.x) + acc.x;
    nx.y = __bfloat162float(h01.y) + __bfloat162float(l01.y) + acc.y;
    nx.z = __bfloat162float(h23.x) + __bfloat162float(l23.x) + acc.z;
    nx.w = __bfloat162float(h23.y) + __bfloat162float(l23.y) + acc.w;

    if (last) {
        // fused mean-pool: sum across 128 channels -> /128
        float s = nx.x + nx.y + nx.z + nx.w;
        #pragma unroll
        for (int off = 16; off > 0; off >>= 1) s += __shfl_down_sync(0xffffffffu, s, off);
        if (lane == 0) d_pooled[warp] = s * (1.f / (float)HC_);
    } else {
        __nv_bfloat16 h0, h1, h2, h3, l0, l1, l2, l3;
        bsplit(nx.x, h0, l0); bsplit(nx.y, h1, l1);
        bsplit(nx.z, h2, l2); bsplit(nx.w, h3, l3);
        uint2 hp, lp;
        hp.x = (uint32_t)__bfloat16_as_ushort(h0) | ((uint32_t)__bfloat16_as_ushort(h1) << 16);
        hp.y = (uint32_t)__bfloat16_as_ushort(h2) | ((uint32_t)__bfloat16_as_ushort(h3) << 16);
        lp.x = (uint32_t)__bfloat16_as_ushort(l0) | ((uint32_t)__bfloat16_as_ushort(l1) << 16);
        lp.y = (uint32_t)__bfloat16_as_ushort(l2) | ((uint32_t)__bfloat16_as_ushort(l3) << 16);
        ((uint2*)d_Xh)[(size_t)warp * 32 + lane] = hp;
        ((uint2*)d_Xl)[(size_t)warp * 32 + lane] = lp;
    }
}

// ---------------- readout ----------------
__global__ void k_final(const float* __restrict__ lw, const float* __restrict__ lb,
                        float* __restrict__ out) {
    __shared__ float sh[128 * NO_];
    int b = blockIdx.x, t = threadIdx.x;
    float acc[NO_];
    #pragma unroll
    for (int j = 0; j < NO_; j++) acc[j] = 0.f;
    for (int tt = t; tt < S_ + R_; tt += 128) {
        float p = d_pooled[b * (S_ + R_) + tt];
        #pragma unroll
        for (int j = 0; j < NO_; j++) acc[j] += p * __ldg(lw + tt * NO_ + j);
    }
    #pragma unroll
    for (int j = 0; j < NO_; j++) sh[t * NO_ + j] = acc[j];
    __syncthreads();
    for (int off = 64; off > 0; off >>= 1) {
        if (t < off) {
            #pragma unroll
            for (int j = 0; j < NO_; j++) sh[t * NO_ + j] += sh[(t + off) * NO_ + j];
        }
        __syncthreads();
    }
    if (t == 0) {
        float z[NO_], sum = 0.f;
        #pragma unroll
        for (int j = 0; j < NO_; j++) { z[j] = expf(sh[j] + lb[j]); sum += z[j]; }
        float inv = 1.f / (sum + 1.f);
        #pragma unroll
        for (int j = 0; j < NO_; j++)
            out[b * NO_ + j] = z[j] * inv * expf(d_O[b * NO_ + j]);
    }
}

// ---------------- host orchestration ----------------
extern "C" void kernel_launch(void* const* d_in, const int* in_sizes, int n_in,
                              void* d_out, int out_size) {
    const float* s_x     = (const float*)d_in[0];
    const float* r_x     = (const float*)d_in[1];
    const int*   ei      = (const int*)d_in[2];
    const float* bn_s_w  = (const float*)d_in[3];
    const float* bn_s_b  = (const float*)d_in[4];
    const float* bn_r_w  = (const float*)d_in[5];
    const float* bn_r_b  = (const float*)d_in[6];
    const float* lin_s_w = (const float*)d_in[7];
    const float* lin_r_w = (const float*)d_in[8];
    const float* conv_w  = (const float*)d_in[9];
    const float* conv_b  = (const float*)d_in[10];
    const float* linr_w  = (const float*)d_in[11];
    const float* linr_b  = (const float*)d_in[12];
    const float* lino_w1 = (const float*)d_in[13];
    const float* lino_b1 = (const float*)d_in[14];
    const float* lino_w2 = (const float*)d_in[15];
    const float* lino_b2 = (const float*)d_in[16];
    float* out = (float*)d_out;

    int E  = in_sizes[2] / 2;
    int Bn = in_sizes[1] / (R_ * (RC_ + 5));
    int n  = Bn * (S_ + R_);
    int rowsS = Bn * S_, rowsR = Bn * R_;
    const int* src = ei;
    const int* dst = ei + E;

    static const int MMA_SMEM = 6 * 32768 + 1024;   // 193 KB (1 CTA/SM, persistent)
    cudaFuncSetAttribute(k_mma, cudaFuncAttributeMaxDynamicSharedMemorySize, MMA_SMEM);

    // encoder chain first (d_stats starts zero: static init + k_prep re-zeroes)
    int nbF = (n + 7) / 8;
    k_stats_s<<<96, 256>>>(s_x, rowsS);                                      // 1
    k_stats_r<<<192, 256>>>(r_x, rowsR);                                     // 2
    k_prep<<<1, 32>>>(bn_s_w, bn_s_b, bn_r_w, bn_r_b, rowsS, rowsR);         // 3
    k_featO<<<nbF + Bn, 256>>>(s_x, r_x, lin_s_w, lin_r_w,                   // 4
                               lino_w1, lino_b1, lino_w2, lino_b2, n, nbF);
    k_wsplit<<<L_, 256>>>(conv_w);                                           // 5
    k_mma<<<148, 128, MMA_SMEM>>>(conv_w, 0, n);                             // 6 (layer 0)

    // CSR build (only needed before first gather)
    k_zero<<<(n + 255) / 256, 256>>>(n);                                     // 7
    k_count<<<(E + 255) / 256, 256>>>(dst, E);                               // 8
    int nb1 = (n + 511) / 512;
    k_scan1<<<nb1, 512>>>(n);                                                // 9 (+dinv)
    k_scan2<<<1, 512>>>(nb1);                                                // 10
    k_scan3<<<(n + 255) / 256, 256>>>(n);                                    // 11
    k_fill<<<(E + 255) / 256, 256>>>(src, dst, E);                           // 12

    // layers
    int gather_blocks = (n * 32 + 255) / 256;
    k_gather<<<gather_blocks, 256>>>(conv_b, n, 0);                          // 13
    for (int l = 1; l < L_; l++) {
        k_mma<<<148, 128, MMA_SMEM>>>(conv_w + (size_t)l * HC_ * HC_, l, n);
        k_gather<<<gather_blocks, 256>>>(conv_b + l * HC_, n, l == L_ - 1);
    }

    // readout (pool fused into last gather)
    k_final<<<Bn, 128>>>(linr_w, linr_b, out);
}

// round 13
// speedup vs baseline: 1.1463x; 1.0007x over previous
#include <cuda_runtime.h>
#include <cuda_bf16.h>
#include <cuda_fp16.h>
#include <cstdint>

#define S_   38
#define R_   340
#define HC_  128
#define SC_  4
#define RC_  3
#define NO_  7
#define L_   4
#define BMAX 512
#define NMAX (BMAX * (S_ + R_))   // 193536
#define EMAX 3072000

// ---------------- scratch (device globals; no allocation allowed) ----------------
__device__ __nv_bfloat16 d_Xh[NMAX * HC_];      // X split hi (49.5 MB) — residual hi
__device__ __nv_bfloat16 d_Xl[NMAX * HC_];      // X split lo (49.5 MB) — residual lo
__device__ __half        d_XWh[NMAX * HC_];     // X @ W in fp16 (49.5 MB, L2-resident)
__device__ int   d_degi[NMAX];
__device__ float d_dinv[NMAX];
__device__ int   d_offs[NMAX];
__device__ int   d_curs[NMAX];
__device__ int   d_bsum[512];
__device__ uint2 d_edge[EMAX];                  // packed (src, norm-bits) per CSR slot
__device__ float d_stats[16];                   // zero-init; re-zeroed by k_prep each call
__device__ float d_pre[16];
__device__ float d_O[BMAX * NO_];
__device__ float d_pooled[NMAX];
// pre-split weights in blocked-swizzled MMA layout (bf16 hi/lo), 32 KB per layer each
__device__ __align__(16) unsigned char d_Wh[L_][32768];
__device__ __align__(16) unsigned char d_Wl[L_][32768];

__device__ __forceinline__ float leaky(float x) { return x > 0.f ? x : 0.2f * x; }

// ================= tcgen05 helpers (verified rounds 5/8/9/10/12) =============
__device__ __forceinline__ uint32_t smem_u32(const void* p) {
    uint32_t a;
    asm("{ .reg .u64 t; cvta.to.shared.u64 t, %1; cvt.u32.u64 %0, t; }" : "=r"(a) : "l"(p));
    return a;
}
__device__ __forceinline__ uint32_t elect_one() {
    uint32_t pred;
    asm volatile("{\n\t.reg .pred p;\n\telect.sync _|p, 0xFFFFFFFF;\n\tselp.b32 %0, 1, 0, p;\n\t}" : "=r"(pred));
    return pred;
}
#define TCG_ALLOC(dst_smem, n) \
    asm volatile("tcgen05.alloc.cta_group::1.sync.aligned.shared::cta.b32 [%0], %1;" \
                 :: "r"(dst_smem), "r"((uint32_t)(n)) : "memory")
#define TCG_DEALLOC(tmem, n) \
    asm volatile("tcgen05.dealloc.cta_group::1.sync.aligned.b32 %0, %1;" :: "r"(tmem), "r"((uint32_t)(n)))
#define TCG_RELINQ() asm volatile("tcgen05.relinquish_alloc_permit.cta_group::1.sync.aligned;")
#define TCG_COMMIT(mbar) \
    asm volatile("tcgen05.commit.cta_group::1.mbarrier::arrive::one.shared::cluster.b64 [%0];" \
                 :: "r"(mbar) : "memory")
#define TCG_FENCE_BEFORE() asm volatile("tcgen05.fence::before_thread_sync;" ::: "memory")
#define TCG_FENCE_AFTER()  asm volatile("tcgen05.fence::after_thread_sync;" ::: "memory")
#define TCG_WAIT_LD() asm volatile("tcgen05.wait::ld.sync.aligned;" ::: "memory")
#define FENCE_ASYNC_SHARED() asm volatile("fence.proxy.async.shared::cta;" ::: "memory")
#define MBAR_INIT(mbar, cnt) \
    asm volatile("mbarrier.init.shared.b64 [%0], %1;" :: "r"(mbar), "r"((uint32_t)(cnt)) : "memory")
#define MBAR_INVAL(mbar) asm volatile("mbarrier.inval.shared.b64 [%0];" :: "r"(mbar) : "memory")

__device__ __forceinline__ void mbar_wait_parity(uint32_t mbar, uint32_t parity) {
    uint32_t done;
    asm volatile("{\n\t.reg .pred p;\n\t"
                 "mbarrier.try_wait.parity.acquire.cta.shared::cta.b64 p, [%1], %2;\n\t"
                 "selp.b32 %0, 1, 0, p;\n\t}"
                 : "=r"(done) : "r"(mbar), "r"(parity) : "memory");
    if (!done) {
        asm volatile("{\n\t.reg .pred P1;\n\t"
                     "WL_%=:\n\t"
                     "mbarrier.try_wait.parity.acquire.cta.shared::cta.b64 P1, [%0], %1, 0x989680;\n\t"
                     "@P1 bra.uni WD_%=;\n\t"
                     "bra.uni WL_%=;\n\t"
                     "WD_%=:\n\t}"
                     :: "r"(mbar), "r"(parity) : "memory");
    }
}

#define TCG_LD_32X32B_X32(r, tmem) \
    asm volatile( \
        "tcgen05.ld.sync.aligned.32x32b.x32.b32 " \
        "{%0, %1, %2, %3, %4, %5, %6, %7, " \
        " %8, %9, %10, %11, %12, %13, %14, %15, " \
        " %16, %17, %18, %19, %20, %21, %22, %23, " \
        " %24, %25, %26, %27, %28, %29, %30, %31}, [%32];" \
        : "=r"((r)[0]),  "=r"((r)[1]),  "=r"((r)[2]),  "=r"((r)[3]), \
          "=r"((r)[4]),  "=r"((r)[5]),  "=r"((r)[6]),  "=r"((r)[7]), \
          "=r"((r)[8]),  "=r"((r)[9]),  "=r"((r)[10]), "=r"((r)[11]), \
          "=r"((r)[12]), "=r"((r)[13]), "=r"((r)[14]), "=r"((r)[15]), \
          "=r"((r)[16]), "=r"((r)[17]), "=r"((r)[18]), "=r"((r)[19]), \
          "=r"((r)[20]), "=r"((r)[21]), "=r"((r)[22]), "=r"((r)[23]), \
          "=r"((r)[24]), "=r"((r)[25]), "=r"((r)[26]), "=r"((r)[27]), \
          "=r"((r)[28]), "=r"((r)[29]), "=r"((r)[30]), "=r"((r)[31]) \
        : "r"(tmem))

// SW128 K-major SMEM descriptor (layout=2, version=1, SBO=64, LBO=1)
static __device__ __forceinline__ uint64_t make_desc(uint32_t addr) {
    return ((uint64_t)2 << 61) | ((uint64_t)1 << 46) | ((uint64_t)64 << 32)
         | ((uint64_t)1 << 16) | (uint64_t)((addr >> 4) & 0x3FFF);
}
__device__ __forceinline__ uint32_t sw128(uint32_t off) { return off ^ ((off >> 3) & 0x70); }

// blocked-atom byte offset for bf16 K-major tile, 128 rows x 128 K-cols
__device__ __forceinline__ uint32_t bf16_off(int row, int col) {
    uint32_t off = (uint32_t)(((row >> 3) + (col >> 6) * 16) * 1024 + (row & 7) * 128 + (col & 63) * 2);
    return sw128(off);
}

#if defined(__CUDA_ARCH_FEAT_SM103_ALL) || !defined(__CUDA_ARCH__)
__device__ __forceinline__ void mma_f16_ss(uint32_t d, uint64_t ad, uint64_t bd,
                                           uint32_t idesc, bool acc) {
    uint32_t en = acc ? 1u : 0u;
    asm volatile(
        "{\n\t.reg .pred p;\n\tsetp.ne.u32 p, %5, 0;\n\t"
        "tcgen05.mma.cta_group::1.kind::f16 [%0], %1, %2, %3, {%4, %4, %4, %4}, p;\n\t}"
        :: "r"(d), "l"(ad), "l"(bd), "r"(idesc), "r"(0u), "r"(en) : "memory");
}
#endif

// idesc: dtype=F32, atype=BF16, btype=BF16, N=128, M=128
#define MMA_IDESC ((1u << 4) | (1u << 7) | (1u << 10) | (16u << 17) | (8u << 24))

// split helper: fp32 -> (hi, lo) bf16
__device__ __forceinline__ void bsplit(float v, __nv_bfloat16& h, __nv_bfloat16& l) {
    h = __float2bfloat16_rn(v);
    l = __float2bfloat16_rn(v - __bfloat162float(h));
}

// ---------------- batchnorm stats (d_stats zeroed by k_prep / static init) --------
__global__ void k_stats_s(const float* __restrict__ sx, int rows) {
    const float4* v4 = (const float4*)sx;
    float s0 = 0, s1 = 0, s2 = 0, s3 = 0, q0 = 0, q1 = 0, q2 = 0, q3 = 0;
    for (int r = blockIdx.x * blockDim.x + threadIdx.x; r < rows; r += gridDim.x * blockDim.x) {
        float4 v = v4[r];
        s0 += v.x; q0 += v.x * v.x;
        s1 += v.y; q1 += v.y * v.y;
        s2 += v.z; q2 += v.z * v.z;
        s3 += v.w; q3 += v.w * v.w;
    }
    #pragma unroll
    for (int off = 16; off > 0; off >>= 1) {
        s0 += __shfl_down_sync(0xffffffffu, s0, off);
        s1 += __shfl_down_sync(0xffffffffu, s1, off);
        s2 += __shfl_down_sync(0xffffffffu, s2, off);
        s3 += __shfl_down_sync(0xffffffffu, s3, off);
        q0 += __shfl_down_sync(0xffffffffu, q0, off);
        q1 += __shfl_down_sync(0xffffffffu, q1, off);
        q2 += __shfl_down_sync(0xffffffffu, q2, off);
        q3 += __shfl_down_sync(0xffffffffu, q3, off);
    }
    if ((threadIdx.x & 31) == 0) {
        atomicAdd(&d_stats[0], s0); atomicAdd(&d_stats[1], s1);
        atomicAdd(&d_stats[2], s2); atomicAdd(&d_stats[3], s3);
        atomicAdd(&d_stats[4], q0); atomicAdd(&d_stats[5], q1);
        atomicAdd(&d_stats[6], q2); atomicAdd(&d_stats[7], q3);
    }
}

__global__ void k_stats_r(const float* __restrict__ rx, int rows) {
    const float4* v4 = (const float4*)rx;
    float s0 = 0, s1 = 0, s2 = 0, q0 = 0, q1 = 0, q2 = 0;
    for (int r = blockIdx.x * blockDim.x + threadIdx.x; r < rows; r += gridDim.x * blockDim.x) {
        float4 v = v4[r * 2];
        s0 += v.x; q0 += v.x * v.x;
        s1 += v.y; q1 += v.y * v.y;
        s2 += v.z; q2 += v.z * v.z;
    }
    #pragma unroll
    for (int off = 16; off > 0; off >>= 1) {
        s0 += __shfl_down_sync(0xffffffffu, s0, off);
        s1 += __shfl_down_sync(0xffffffffu, s1, off);
        s2 += __shfl_down_sync(0xffffffffu, s2, off);
        q0 += __shfl_down_sync(0xffffffffu, q0, off);
        q1 += __shfl_down_sync(0xffffffffu, q1, off);
        q2 += __shfl_down_sync(0xffffffffu, q2, off);
    }
    if ((threadIdx.x & 31) == 0) {
        atomicAdd(&d_stats[8],  s0); atomicAdd(&d_stats[9],  s1);
        atomicAdd(&d_stats[10], s2); atomicAdd(&d_stats[11], q0);
        atomicAdd(&d_stats[12], q1); atomicAdd(&d_stats[13], q2);
    }
}

// computes bn scale/shift, then re-zeroes d_stats for the next graph replay
__global__ void k_prep(const float* __restrict__ bsw, const float* __restrict__ bsb,
                       const float* __restrict__ brw, const float* __restrict__ brb,
                       int ns, int nr) {
    int t = threadIdx.x;
    if (t < 4) {
        float m = d_stats[t] / (float)ns;
        float var = d_stats[4 + t] / (float)ns - m * m;
        float sc = rsqrtf(var + 1e-5f) * bsw[t];
        d_pre[t] = sc;
        d_pre[4 + t] = bsb[t] - m * sc;
    } else if (t < 7) {
        int c = t - 4;
        float m = d_stats[8 + c] / (float)nr;
        float var = d_stats[11 + c] / (float)nr - m * m;
        float sc = rsqrtf(var + 1e-5f) * brw[c];
        d_pre[8 + c] = sc;
        d_pre[11 + c] = brb[c] - m * sc;
    }
    __syncthreads();
    if (t < 16) d_stats[t] = 0.f;
}

// -------- feature encoder (warp-per-node, bn folded into smem weights) + o-branch --
// blocks [0, nbF): 8 nodes each (one per warp). blocks [nbF, nbF+Bn): o-branch.
__global__ void __launch_bounds__(256) k_featO(
        const float* __restrict__ sx, const float* __restrict__ rx,
        const float* __restrict__ wsl, const float* __restrict__ wrl,
        const float* __restrict__ w1, const float* __restrict__ b1,
        const float* __restrict__ w2, const float* __restrict__ b2,
        int n, int nbF) {
    int tid = threadIdx.x;
    if ((int)blockIdx.x < nbF) {
        __shared__ float ws[SC_ * HC_];   // scaled s-weights
        __shared__ float wr[RC_ * HC_];   // scaled r-weights
        __shared__ float bs[HC_], br[HC_];
        for (int i = tid; i < SC_ * HC_; i += 256)
            ws[i] = __ldg(wsl + i) * d_pre[i >> 7];
        for (int i = tid; i < RC_ * HC_; i += 256)
            wr[i] = __ldg(wrl + i) * d_pre[8 + (i >> 7)];
        if (tid < HC_) {
            float as = 0.f, ar = 0.f;
            #pragma unroll
            for (int c = 0; c < SC_; c++) as += d_pre[4 + c] * __ldg(wsl + c * HC_ + tid);
            #pragma unroll
            for (int c = 0; c < RC_; c++) ar += d_pre[11 + c] * __ldg(wrl + c * HC_ + tid);
            bs[tid] = as;
            br[tid] = ar;
        }
        __syncthreads();
        int wid = tid >> 5, lane = tid & 31;
        int node = blockIdx.x * 8 + wid;
        if (node >= n) return;
        int b = node / (S_ + R_);
        int pos = node - b * (S_ + R_);
        float4 xv = make_float4(0.f, 0.f, 0.f, 0.f);
        if (lane == 0) {
            if (pos < S_) xv = ((const float4*)sx)[b * S_ + pos];
            else          xv = ((const float4*)rx)[(size_t)(b * R_ + pos - S_) * 2];
        }
        float x0 = __shfl_sync(0xffffffffu, xv.x, 0);
        float x1 = __shfl_sync(0xffffffffu, xv.y, 0);
        float x2 = __shfl_sync(0xffffffffu, xv.z, 0);
        float x3 = __shfl_sync(0xffffffffu, xv.w, 0);
        float4 a;
        if (pos < S_) {
            float4 w0 = ((float4*)ws)[lane];
            float4 w1v = ((float4*)ws)[32 + lane];
            float4 w2v = ((float4*)ws)[64 + lane];
            float4 w3v = ((float4*)ws)[96 + lane];
            float4 bb = ((float4*)bs)[lane];
            a.x = bb.x + x0 * w0.x + x1 * w1v.x + x2 * w2v.x + x3 * w3v.x;
            a.y = bb.y + x0 * w0.y + x1 * w1v.y + x2 * w2v.y + x3 * w3v.y;
            a.z = bb.z + x0 * w0.z + x1 * w1v.z + x2 * w2v.z + x3 * w3v.z;
            a.w = bb.w + x0 * w0.w + x1 * w1v.w + x2 * w2v.w + x3 * w3v.w;
        } else {
            float4 w0 = ((float4*)wr)[lane];
            float4 w1v = ((float4*)wr)[32 + lane];
            float4 w2v = ((float4*)wr)[64 + lane];
            float4 bb = ((float4*)br)[lane];
            a.x = bb.x + x0 * w0.x + x1 * w1v.x + x2 * w2v.x;
            a.y = bb.y + x0 * w0.y + x1 * w1v.y + x2 * w2v.y;
            a.z = bb.z + x0 * w0.z + x1 * w1v.z + x2 * w2v.z;
            a.w = bb.w + x0 * w0.w + x1 * w1v.w + x2 * w2v.w;
        }
        a.x = leaky(a.x); a.y = leaky(a.y); a.z = leaky(a.z); a.w = leaky(a.w);
        __nv_bfloat16 h0, h1, h2, h3, l0, l1, l2, l3;
        bsplit(a.x, h0, l0); bsplit(a.y, h1, l1);
        bsplit(a.z, h2, l2); bsplit(a.w, h3, l3);
        uint2 hp, lp;
        hp.x = (uint32_t)__bfloat16_as_ushort(h0) | ((uint32_t)__bfloat16_as_ushort(h1) << 16);
        hp.y = (uint32_t)__bfloat16_as_ushort(h2) | ((uint32_t)__bfloat16_as_ushort(h3) << 16);
        lp.x = (uint32_t)__bfloat16_as_ushort(l0) | ((uint32_t)__bfloat16_as_ushort(l1) << 16);
        lp.y = (uint32_t)__bfloat16_as_ushort(l2) | ((uint32_t)__bfloat16_as_ushort(l3) << 16);
        ((uint2*)d_Xh)[(size_t)node * 32 + lane] = hp;
        ((uint2*)d_Xl)[(size_t)node * 32 + lane] = lp;
    } else {
        __shared__ float sh[HC_];
        int b = blockIdx.x - nbF;
        int h = tid;
        if (h < HC_) {
            float acc = b1[h];
            #pragma unroll
            for (int c = 0; c < 5; c++)
                acc += __ldg(rx + (size_t)(b * R_) * (RC_ + 5) + RC_ + c) * __ldg(w1 + c * HC_ + h);
            sh[h] = leaky(acc);
        }
        __syncthreads();
        if (h < NO_) {
            float o = b2[h];
            #pragma unroll 8
            for (int k = 0; k < HC_; k++) o += sh[k] * __ldg(w2 + k * NO_ + h);
            d_O[b * NO_ + h] = o;
        }
    }
}

// ---------------- W split precompute (once; all layers) ----------------
__global__ void k_wsplit(const float* __restrict__ conv_w) {
    int l = blockIdx.x;
    const float* W = conv_w + (size_t)l * HC_ * HC_;
    for (int i = threadIdx.x; i < HC_ * HC_; i += blockDim.x) {
        int k = i >> 7, nn = i & 127;
        float v = __ldg(W + k * 128 + nn);
        __nv_bfloat16 h, lo;
        bsplit(v, h, lo);
        uint32_t off = bf16_off(nn, k);   // B[n][k] = W[k][n]
        *(__nv_bfloat16*)(d_Wh[l] + off) = h;
        *(__nv_bfloat16*)(d_Wl[l] + off) = lo;
    }
}

// ---------------- init / degree / CSR ----------------
__global__ void k_zero(int n) {
    int i = blockIdx.x * blockDim.x + threadIdx.x;
    if (i < n) d_degi[i] = 0;
}

__global__ void k_count(const int* __restrict__ dst, int E) {
    int e = blockIdx.x * blockDim.x + threadIdx.x;
    if (e < E) atomicAdd(&d_degi[dst[e]], 1);
}

// scan1 also emits dinv (folded former k_dinv pass)
__global__ void k_scan1(int n) {
    __shared__ int sh[512];
    int t = threadIdx.x;
    int g = blockIdx.x * 512 + t;
    int v = (g < n) ? d_degi[g] : 0;
    if (g < n) d_dinv[g] = rsqrtf((float)(v + 1));
    sh[t] = v;
    __syncthreads();
    #pragma unroll
    for (int off = 1; off < 512; off <<= 1) {
        int a = sh[t];
        int b = (t >= off) ? sh[t - off] : 0;
        __syncthreads();
        sh[t] = a + b;
        __syncthreads();
    }
    if (g < n) d_offs[g] = sh[t] - v;
    if (t == 511) d_bsum[blockIdx.x] = sh[511];
}

__global__ void k_scan2(int nb) {
    __shared__ int sh[512];
    int t = threadIdx.x;
    int v = (t < nb) ? d_bsum[t] : 0;
    sh[t] = v;
    __syncthreads();
    #pragma unroll
    for (int off = 1; off < 512; off <<= 1) {
        int a = sh[t];
        int b = (t >= off) ? sh[t - off] : 0;
        __syncthreads();
        sh[t] = a + b;
        __syncthreads();
    }
    if (t < nb) d_bsum[t] = sh[t] - v;
}

__global__ void k_scan3(int n) {
    int g = blockIdx.x * blockDim.x + threadIdx.x;
    if (g < n) {
        int o = d_offs[g] + d_bsum[g >> 9];
        d_offs[g] = o;
        d_curs[g] = o;
    }
}

__global__ void k_fill(const int* __restrict__ src, const int* __restrict__ dst, int E) {
    int e = blockIdx.x * blockDim.x + threadIdx.x;
    if (e < E) {
        int s = src[e], d = dst[e];
        int p = atomicAdd(&d_curs[d], 1);
        float nw = d_dinv[s] * d_dinv[d];
        d_edge[p] = make_uint2((uint32_t)s, __float_as_uint(nw));
    }
}

// =============== persistent pipelined tcgen05 bf16x3 GEMM: XWh = fp16(X @ W) ======
__global__ void __launch_bounds__(128) k_mma(const float* __restrict__ W, int layer, int n) {
    extern __shared__ char dyn_smem[];
#if defined(__CUDA_ARCH_FEAT_SM103_ALL) || !defined(__CUDA_ARCH__)
    __shared__ uint32_t s_tmem[2];
    __shared__ __align__(8) unsigned long long s_mbar[2];

    char* base = (char*)(((uintptr_t)dyn_smem + 1023) & ~(uintptr_t)1023);
    char* A0h = base;
    char* A0l = base + 32768;
    char* A1h = base + 65536;
    char* A1l = base + 98304;
    char* Bh  = base + 131072;
    char* Bl  = base + 163840;   // total 192 KB

    int tid = threadIdx.x, wid = tid >> 5, lane = tid & 31;

    if (wid == 0) TCG_ALLOC(smem_u32(s_tmem), 256);
    if (tid == 0) {
        MBAR_INIT(smem_u32(&s_mbar[0]), 1);
        MBAR_INIT(smem_u32(&s_mbar[1]), 1);
    }
    __syncthreads();
    uint32_t tmem;
    asm volatile("ld.shared.b32 %0, [%1];" : "=r"(tmem) : "r"(smem_u32(s_tmem)));

    // stage pre-split W (coalesced uint4 copy, once per CTA)
    {
        const uint4* gh = (const uint4*)d_Wh[layer];
        const uint4* gl = (const uint4*)d_Wl[layer];
        uint4* sh = (uint4*)Bh;
        uint4* sl = (uint4*)Bl;
        for (int i = tid; i < 2048; i += 128) { sh[i] = gh[i]; sl[i] = gl[i]; }
    }

    const uint64_t bdh = make_desc(smem_u32(Bh));
    const uint64_t bdl = make_desc(smem_u32(Bl));
    const uint4* GXh = (const uint4*)d_Xh;   // row = 16 uint4 (128 bf16)
    const uint4* GXl = (const uint4*)d_Xl;
    __half* XWh = d_XWh;

    int tiles = (n + 127) >> 7;
    uint32_t ph0 = 0, ph1 = 0;
    int j = 0, prev_t = -1;

    for (int t = blockIdx.x; t < tiles; t += gridDim.x, j++) {
        int buf = j & 1;
        char* Ah = buf ? A1h : A0h;
        char* Al = buf ? A1l : A0l;
        int row0 = t << 7;

        // --- stage A tile: swizzled uint4 copy (overlaps in-flight MMA[j-1]) ---
        #pragma unroll 4
        for (int i = tid; i < 2048; i += 128) {          // 128 rows x 16 quads
            int row = i >> 4, q = i & 15;
            uint4 vh = make_uint4(0u, 0u, 0u, 0u), vl = vh;
            if (row0 + row < n) {
                size_t gi = (size_t)(row0 + row) * 16 + q;
                vh = __ldg(GXh + gi);
                vl = __ldg(GXl + gi);
            }
            uint32_t off = bf16_off(row, q * 8);
            *(uint4*)(Ah + off) = vh;
            *(uint4*)(Al + off) = vl;
        }
        TCG_FENCE_BEFORE();
        __syncthreads();

        // --- wait for MMA[j-1] ---
        if (j > 0) {
            if (buf) { mbar_wait_parity(smem_u32(&s_mbar[0]), ph0); ph0 ^= 1; }
            else     { mbar_wait_parity(smem_u32(&s_mbar[1]), ph1); ph1 ^= 1; }
            TCG_FENCE_AFTER();
        }

        // --- issue MMA[j] ---
        if (wid == 0) {
            TCG_FENCE_AFTER();
            if (elect_one()) {
                FENCE_ASYNC_SHARED();
                uint64_t adh = make_desc(smem_u32(Ah));
                uint64_t adl = make_desc(smem_u32(Al));
                uint32_t D = tmem + buf * 128;
                #pragma unroll
                for (int s = 0; s < 8; s++) {
                    uint64_t off = (uint64_t)((s & 3) * 2 + (s >> 2) * 1024);
                    mma_f16_ss(D, adh + off, bdh + off, MMA_IDESC, s > 0);
                }
                #pragma unroll
                for (int s = 0; s < 8; s++) {
                    uint64_t off = (uint64_t)((s & 3) * 2 + (s >> 2) * 1024);
                    mma_f16_ss(D, adl + off, bdh + off, MMA_IDESC, true);
                }
                #pragma unroll
                for (int s = 0; s < 8; s++) {
                    uint64_t off = (uint64_t)((s & 3) * 2 + (s >> 2) * 1024);
                    mma_f16_ss(D, adh + off, bdl + off, MMA_IDESC, true);
                }
                TCG_COMMIT(smem_u32(&s_mbar[buf]));
            }
        }

        // --- epilogue for tile j-1 (overlaps MMA[j]); fp16 output ---
        if (j > 0) {
            int prow = (prev_t << 7) + wid * 32 + lane;
            uint32_t Dp = tmem + (1 - buf) * 128;
            uint32_t r[32];
            #pragma unroll
            for (int c0 = 0; c0 < 128; c0 += 32) {
                TCG_LD_32X32B_X32(r, Dp + c0);
                TCG_WAIT_LD();
                if (prow < n) {
                    uint32_t h2[16];
                    #pragma unroll
                    for (int k = 0; k < 16; k++) {
                        __half2 p = __floats2half2_rn(__uint_as_float(r[2 * k]),
                                                      __uint_as_float(r[2 * k + 1]));
                        h2[k] = *(uint32_t*)&p;
                    }
                    uint4* dst = (uint4*)(XWh + (size_t)prow * 128 + c0);
                    dst[0] = make_uint4(h2[0], h2[1], h2[2], h2[3]);
                    dst[1] = make_uint4(h2[4], h2[5], h2[6], h2[7]);
                    dst[2] = make_uint4(h2[8], h2[9], h2[10], h2[11]);
                    dst[3] = make_uint4(h2[12], h2[13], h2[14], h2[15]);
                }
            }
            TCG_FENCE_BEFORE();
        }
        prev_t = t;
    }

    // --- drain last tile ---
    if (j > 0) {
        int buf = (j - 1) & 1;
        if (buf) { mbar_wait_parity(smem_u32(&s_mbar[1]), ph1); ph1 ^= 1; }
        else     { mbar_wait_parity(smem_u32(&s_mbar[0]), ph0); ph0 ^= 1; }
        TCG_FENCE_AFTER();
        int prow = (prev_t << 7) + wid * 32 + lane;
        uint32_t Dp = tmem + buf * 128;
        uint32_t r[32];
        #pragma unroll
        for (int c0 = 0; c0 < 128; c0 += 32) {
            TCG_LD_32X32B_X32(r, Dp + c0);
            TCG_WAIT_LD();
            if (prow < n) {
                uint32_t h2[16];
                #pragma unroll
                for (int k = 0; k < 16; k++) {
                    __half2 p = __floats2half2_rn(__uint_as_float(r[2 * k]),
                                                  __uint_as_float(r[2 * k + 1]));
                    h2[k] = *(uint32_t*)&p;
                }
                uint4* dst = (uint4*)(XWh + (size_t)prow * 128 + c0);
                dst[0] = make_uint4(h2[0], h2[1], h2[2], h2[3]);
                dst[1] = make_uint4(h2[4], h2[5], h2[6], h2[7]);
                dst[2] = make_uint4(h2[8], h2[9], h2[10], h2[11]);
                dst[3] = make_uint4(h2[12], h2[13], h2[14], h2[15]);
            }
        }
        TCG_FENCE_BEFORE();
    }
    __syncthreads();
    if (wid == 0) {
        if (elect_one()) {
            MBAR_INVAL(smem_u32(&s_mbar[0]));
            MBAR_INVAL(smem_u32(&s_mbar[1]));
        }
        TCG_RELINQ();
        TCG_DEALLOC(tmem, 256);
    }
#else
    // fp32 fallback for the non-'a' gencode pass (never selected at runtime on GB300)
    float* Ws = (float*)(((uintptr_t)dyn_smem + 1023) & ~(uintptr_t)1023);  // 64 KB
    int tid = threadIdx.x;
    for (int i = tid; i < 128 * 128; i += 128) Ws[i] = __ldg(W + i);
    __syncthreads();
    int tiles = (n + 127) >> 7;
    for (int t = blockIdx.x; t < tiles; t += gridDim.x) {
        int row = (t << 7) + tid;
        if (row < n) {
            for (int c0 = 0; c0 < 128; c0 += 16) {
                float acc[16];
                #pragma unroll
                for (int jj = 0; jj < 16; jj++) acc[jj] = 0.f;
                for (int k = 0; k < 128; k++) {
                    float a = __bfloat162float(d_Xh[(size_t)row * 128 + k])
                            + __bfloat162float(d_Xl[(size_t)row * 128 + k]);
                    #pragma unroll
                    for (int jj = 0; jj < 16; jj++) acc[jj] += a * Ws[k * 128 + c0 + jj];
                }
                #pragma unroll
                for (int jj = 0; jj < 16; jj++)
                    d_XWh[(size_t)row * 128 + c0 + jj] = __float2half_rn(acc[jj]);
            }
        }
    }
#endif
}

// ------- fused gather(fp16 XW) + self-loop + bias + leaky + residual (+pool) -------
__global__ void k_gather(const float* __restrict__ bias, int n, int last) {
    int warp = (blockIdx.x * blockDim.x + threadIdx.x) >> 5;
    int lane = threadIdx.x & 31;
    if (warp >= n) return;
    int cnt = d_degi[warp];
    int start = d_offs[warp];
    float di = d_dinv[warp];
    const uint2* xw2 = (const uint2*)d_XWh;   // 4 halves per uint2; row stride 32

    // self loop
    uint2 sp = xw2[(size_t)warp * 32 + lane];
    float2 sa = __half22float2(*(__half2*)&sp.x);
    float2 sb = __half22float2(*(__half2*)&sp.y);
    float ns = di * di;
    float4 acc = make_float4(sa.x * ns, sa.y * ns, sb.x * ns, sb.y * ns);

    int j = 0;
    for (; j + 4 <= cnt; j += 4) {
        uint2 e0 = __ldg(d_edge + start + j);
        uint2 e1 = __ldg(d_edge + start + j + 1);
        uint2 e2 = __ldg(d_edge + start + j + 2);
        uint2 e3 = __ldg(d_edge + start + j + 3);
        uint2 v0 = __ldg(xw2 + (size_t)e0.x * 32 + lane);
        uint2 v1 = __ldg(xw2 + (size_t)e1.x * 32 + lane);
        uint2 v2 = __ldg(xw2 + (size_t)e2.x * 32 + lane);
        uint2 v3 = __ldg(xw2 + (size_t)e3.x * 32 + lane);
        float n0 = __uint_as_float(e0.y), n1 = __uint_as_float(e1.y);
        float n2 = __uint_as_float(e2.y), n3 = __uint_as_float(e3.y);
        float2 a0 = __half22float2(*(__half2*)&v0.x), b0 = __half22float2(*(__half2*)&v0.y);
        float2 a1 = __half22float2(*(__half2*)&v1.x), b1 = __half22float2(*(__half2*)&v1.y);
        float2 a2 = __half22float2(*(__half2*)&v2.x), b2 = __half22float2(*(__half2*)&v2.y);
        float2 a3 = __half22float2(*(__half2*)&v3.x), b3 = __half22float2(*(__half2*)&v3.y);
        acc.x += n0 * a0.x + n1 * a1.x + n2 * a2.x + n3 * a3.x;
        acc.y += n0 * a0.y + n1 * a1.y + n2 * a2.y + n3 * a3.y;
        acc.z += n0 * b0.x + n1 * b1.x + n2 * b2.x + n3 * b3.x;
        acc.w += n0 * b0.y + n1 * b1.y + n2 * b2.y + n3 * b3.y;
    }
    for (; j < cnt; j++) {
        uint2 e0 = __ldg(d_edge + start + j);
        uint2 v0 = __ldg(xw2 + (size_t)e0.x * 32 + lane);
        float n0 = __uint_as_float(e0.y);
        float2 a0 = __half22float2(*(__half2*)&v0.x), b0 = __half22float2(*(__half2*)&v0.y);
        acc.x += n0 * a0.x;
        acc.y += n0 * a0.y;
        acc.z += n0 * b0.x;
        acc.w += n0 * b0.y;
    }

    float4 bv = ((const float4*)bias)[lane];
    acc.x = leaky(acc.x + bv.x);
    acc.y = leaky(acc.y + bv.y);
    acc.z = leaky(acc.z + bv.z);
    acc.w = leaky(acc.w + bv.w);

    // residual from bf16 hi/lo pair
    uint2 xh = __ldg(((const uint2*)d_Xh) + (size_t)warp * 32 + lane);
    uint2 xl = __ldg(((const uint2*)d_Xl) + (size_t)warp * 32 + lane);
    __nv_bfloat162 h01 = *(__nv_bfloat162*)&xh.x, h23 = *(__nv_bfloat162*)&xh.y;
    __nv_bfloat162 l01 = *(__nv_bfloat162*)&xl.x, l23 = *(__nv_bfloat162*)&xl.y;
    float4 nx;
    nx.x = __bfloat162float(h01.x) + __bfloat162float(l01.x) + acc.x;
    nx.y = __bfloat162float(h01.y) + __bfloat162float(l01.y) + acc.y;
    nx.z = __bfloat162float(h23.x) + __bfloat162float(l23.x) + acc.z;
    nx.w = __bfloat162float(h23.y) + __bfloat162float(l23.y) + acc.w;

    if (last) {
        // fused mean-pool: sum across 128 channels -> /128
        float s = nx.x + nx.y + nx.z + nx.w;
        #pragma unroll
        for (int off = 16; off > 0; off >>= 1) s += __shfl_down_sync(0xffffffffu, s, off);
        if (lane == 0) d_pooled[warp] = s * (1.f / (float)HC_);
    } else {
        __nv_bfloat16 h0, h1, h2, h3, l0, l1, l2, l3;
        bsplit(nx.x, h0, l0); bsplit(nx.y, h1, l1);
        bsplit(nx.z, h2, l2); bsplit(nx.w, h3, l3);
        uint2 hp, lp;
        hp.x = (uint32_t)__bfloat16_as_ushort(h0) | ((uint32_t)__bfloat16_as_ushort(h1) << 16);
        hp.y = (uint32_t)__bfloat16_as_ushort(h2) | ((uint32_t)__bfloat16_as_ushort(h3) << 16);
        lp.x = (uint32_t)__bfloat16_as_ushort(l0) | ((uint32_t)__bfloat16_as_ushort(l1) << 16);
        lp.y = (uint32_t)__bfloat16_as_ushort(l2) | ((uint32_t)__bfloat16_as_ushort(l3) << 16);
        ((uint2*)d_Xh)[(size_t)warp * 32 + lane] = hp;
        ((uint2*)d_Xl)[(size_t)warp * 32 + lane] = lp;
    }
}

// ---------------- readout ----------------
__global__ void k_final(const float* __restrict__ lw, const float* __restrict__ lb,
                        float* __restrict__ out) {
    __shared__ float sh[128 * NO_];
    int b = blockIdx.x, t = threadIdx.x;
    float acc[NO_];
    #pragma unroll
    for (int j = 0; j < NO_; j++) acc[j] = 0.f;
    for (int tt = t; tt < S_ + R_; tt += 128) {
        float p = d_pooled[b * (S_ + R_) + tt];
        #pragma unroll
        for (int j = 0; j < NO_; j++) acc[j] += p * __ldg(lw + tt * NO_ + j);
    }
    #pragma unroll
    for (int j = 0; j < NO_; j++) sh[t * NO_ + j] = acc[j];
    __syncthreads();
    for (int off = 64; off > 0; off >>= 1) {
        if (t < off) {
            #pragma unroll
            for (int j = 0; j < NO_; j++) sh[t * NO_ + j] += sh[(t + off) * NO_ + j];
        }
        __syncthreads();
    }
    if (t == 0) {
        float z[NO_], sum = 0.f;
        #pragma unroll
        for (int j = 0; j < NO_; j++) { z[j] = expf(sh[j] + lb[j]); sum += z[j]; }
        float inv = 1.f / (sum + 1.f);
        #pragma unroll
        for (int j = 0; j < NO_; j++)
            out[b * NO_ + j] = z[j] * inv * expf(d_O[b * NO_ + j]);
    }
}

// ---------------- host orchestration (fork-join: CSR overlaps encoder+mma0) -------
extern "C" void kernel_launch(void* const* d_in, const int* in_sizes, int n_in,
                              void* d_out, int out_size) {
    const float* s_x     = (const float*)d_in[0];
    const float* r_x     = (const float*)d_in[1];
    const int*   ei      = (const int*)d_in[2];
    const float* bn_s_w  = (const float*)d_in[3];
    const float* bn_s_b  = (const float*)d_in[4];
    const float* bn_r_w  = (const float*)d_in[5];
    const float* bn_r_b  = (const float*)d_in[6];
    const float* lin_s_w = (const float*)d_in[7];
    const float* lin_r_w = (const float*)d_in[8];
    const float* conv_w  = (const float*)d_in[9];
    const float* conv_b  = (const float*)d_in[10];
    const float* linr_w  = (const float*)d_in[11];
    const float* linr_b  = (const float*)d_in[12];
    const float* lino_w1 = (const float*)d_in[13];
    const float* lino_b1 = (const float*)d_in[14];
    const float* lino_w2 = (const float*)d_in[15];
    const float* lino_b2 = (const float*)d_in[16];
    float* out = (float*)d_out;

    int E  = in_sizes[2] / 2;
    int Bn = in_sizes[1] / (R_ * (RC_ + 5));
    int n  = Bn * (S_ + R_);
    int rowsS = Bn * S_, rowsR = Bn * R_;
    const int* src = ei;
    const int* dst = ei + E;

    static const int MMA_SMEM = 6 * 32768 + 1024;   // 193 KB (1 CTA/SM, persistent)

    // one-time infra init (streams/events; no device memory involved)
    static cudaStream_t sB = 0;
    static cudaEvent_t evFork = 0, evJoin = 0;
    static bool inited = false;
    if (!inited) {
        cudaFuncSetAttribute(k_mma, cudaFuncAttributeMaxDynamicSharedMemorySize, MMA_SMEM);
        if (cudaStreamCreateWithFlags(&sB, cudaStreamNonBlocking) != cudaSuccess) sB = 0;
        if (sB) {
            if (cudaEventCreateWithFlags(&evFork, cudaEventDisableTiming) != cudaSuccess ||
                cudaEventCreateWithFlags(&evJoin, cudaEventDisableTiming) != cudaSuccess) {
                sB = 0;
            }
        }
        inited = true;
    }

    int nbF = (n + 7) / 8;
    int nb1 = (n + 511) / 512;
    bool fork = (sB != 0);

    // ---- fork: CSR chain on side stream (depends only on edge_index) ----
    if (fork) {
        cudaEventRecord(evFork, 0);
        cudaStreamWaitEvent(sB, evFork, 0);
        k_zero<<<(n + 255) / 256, 256, 0, sB>>>(n);
        k_count<<<(E + 255) / 256, 256, 0, sB>>>(dst, E);
        k_scan1<<<nb1, 512, 0, sB>>>(n);
        k_scan2<<<1, 512, 0, sB>>>(nb1);
        k_scan3<<<(n + 255) / 256, 256, 0, sB>>>(n);
        k_fill<<<(E + 255) / 256, 256, 0, sB>>>(src, dst, E);
        cudaEventRecord(evJoin, sB);
    }

    // ---- main stream: encoder chain + layer-0 GEMM (independent of CSR) ----
    k_stats_s<<<96, 256>>>(s_x, rowsS);
    k_stats_r<<<192, 256>>>(r_x, rowsR);
    k_prep<<<1, 32>>>(bn_s_w, bn_s_b, bn_r_w, bn_r_b, rowsS, rowsR);
    k_featO<<<nbF + Bn, 256>>>(s_x, r_x, lin_s_w, lin_r_w,
                               lino_w1, lino_b1, lino_w2, lino_b2, n, nbF);
    k_wsplit<<<L_, 256>>>(conv_w);
    k_mma<<<148, 128, MMA_SMEM>>>(conv_w, 0, n);

    if (fork) {
        cudaStreamWaitEvent(0, evJoin, 0);
    } else {
        // serial fallback: CSR chain on main stream
        k_zero<<<(n + 255) / 256, 256>>>(n);
        k_count<<<(E + 255) / 256, 256>>>(dst, E);
        k_scan1<<<nb1, 512>>>(n);
        k_scan2<<<1, 512>>>(nb1);
        k_scan3<<<(n + 255) / 256, 256>>>(n);
        k_fill<<<(E + 255) / 256, 256>>>(src, dst, E);
    }

    // ---- layers ----
    int gather_blocks = (n * 32 + 255) / 256;
    k_gather<<<gather_blocks, 256>>>(conv_b, n, 0);
    for (int l = 1; l < L_; l++) {
        k_mma<<<148, 128, MMA_SMEM>>>(conv_w + (size_t)l * HC_ * HC_, l, n);
        k_gather<<<gather_blocks, 256>>>(conv_b + l * HC_, n, l == L_ - 1);
    }

    // readout (pool fused into last gather)
    k_final<<<Bn, 128>>>(linr_w, linr_b, out);
}

// round 14
// speedup vs baseline: 1.3593x; 1.1859x over previous
#include <cuda_runtime.h>
#include <cuda_bf16.h>
#include <cuda_fp16.h>
#include <cstdint>

#define S_   38
#define R_   340
#define HC_  128
#define SC_  4
#define RC_  3
#define NO_  7
#define L_   4
#define BMAX 512
#define NMAX (BMAX * (S_ + R_))   // 193536
#define EMAX 3072000

// ---------------- scratch (device globals; no allocation allowed) ----------------
__device__ __nv_bfloat16 d_Xh[NMAX * HC_];      // X split hi (49.5 MB) — residual hi + GEMM A
__device__ __nv_bfloat16 d_Xl[NMAX * HC_];      // X split lo (49.5 MB) — residual lo only
__device__ __half        d_XWh[NMAX * HC_];     // X @ W in fp16 (49.5 MB, L2-resident)
__device__ int   d_degi[NMAX];
__device__ float d_dinv[NMAX];
__device__ int   d_offs[NMAX];
__device__ int   d_curs[NMAX];
__device__ int   d_bsum[512];
__device__ uint2 d_edge[EMAX];                  // packed (src, norm-bits) per CSR slot
__device__ float d_stats[16];                   // zero-init; re-zeroed by k_prep each call
__device__ float d_pre[16];
__device__ float d_O[BMAX * NO_];
__device__ float d_pooled[NMAX];
// pre-split weights in blocked-swizzled MMA layout (bf16 hi/lo), 32 KB per layer each
__device__ __align__(16) unsigned char d_Wh[L_][32768];
__device__ __align__(16) unsigned char d_Wl[L_][32768];

__device__ __forceinline__ float leaky(float x) { return x > 0.f ? x : 0.2f * x; }

// ================= tcgen05 helpers (verified rounds 5/8/9/10/12) =============
__device__ __forceinline__ uint32_t smem_u32(const void* p) {
    uint32_t a;
    asm("{ .reg .u64 t; cvta.to.shared.u64 t, %1; cvt.u32.u64 %0, t; }" : "=r"(a) : "l"(p));
    return a;
}
__device__ __forceinline__ uint32_t elect_one() {
    uint32_t pred;
    asm volatile("{\n\t.reg .pred p;\n\telect.sync _|p, 0xFFFFFFFF;\n\tselp.b32 %0, 1, 0, p;\n\t}" : "=r"(pred));
    return pred;
}
#define TCG_ALLOC(dst_smem, n) \
    asm volatile("tcgen05.alloc.cta_group::1.sync.aligned.shared::cta.b32 [%0], %1;" \
                 :: "r"(dst_smem), "r"((uint32_t)(n)) : "memory")
#define TCG_DEALLOC(tmem, n) \
    asm volatile("tcgen05.dealloc.cta_group::1.sync.aligned.b32 %0, %1;" :: "r"(tmem), "r"((uint32_t)(n)))
#define TCG_RELINQ() asm volatile("tcgen05.relinquish_alloc_permit.cta_group::1.sync.aligned;")
#define TCG_COMMIT(mbar) \
    asm volatile("tcgen05.commit.cta_group::1.mbarrier::arrive::one.shared::cluster.b64 [%0];" \
                 :: "r"(mbar) : "memory")
#define TCG_FENCE_BEFORE() asm volatile("tcgen05.fence::before_thread_sync;" ::: "memory")
#define TCG_FENCE_AFTER()  asm volatile("tcgen05.fence::after_thread_sync;" ::: "memory")
#define TCG_WAIT_LD() asm volatile("tcgen05.wait::ld.sync.aligned;" ::: "memory")
#define FENCE_ASYNC_SHARED() asm volatile("fence.proxy.async.shared::cta;" ::: "memory")
#define MBAR_INIT(mbar, cnt) \
    asm volatile("mbarrier.init.shared.b64 [%0], %1;" :: "r"(mbar), "r"((uint32_t)(cnt)) : "memory")
#define MBAR_INVAL(mbar) asm volatile("mbarrier.inval.shared.b64 [%0];" :: "r"(mbar) : "memory")

__device__ __forceinline__ void mbar_wait_parity(uint32_t mbar, uint32_t parity) {
    uint32_t done;
    asm volatile("{\n\t.reg .pred p;\n\t"
                 "mbarrier.try_wait.parity.acquire.cta.shared::cta.b64 p, [%1], %2;\n\t"
                 "selp.b32 %0, 1, 0, p;\n\t}"
                 : "=r"(done) : "r"(mbar), "r"(parity) : "memory");
    if (!done) {
        asm volatile("{\n\t.reg .pred P1;\n\t"
                     "WL_%=:\n\t"
                     "mbarrier.try_wait.parity.acquire.cta.shared::cta.b64 P1, [%0], %1, 0x989680;\n\t"
                     "@P1 bra.uni WD_%=;\n\t"
                     "bra.uni WL_%=;\n\t"
                     "WD_%=:\n\t}"
                     :: "r"(mbar), "r"(parity) : "memory");
    }
}

#define TCG_LD_32X32B_X32(r, tmem) \
    asm volatile( \
        "tcgen05.ld.sync.aligned.32x32b.x32.b32 " \
        "{%0, %1, %2, %3, %4, %5, %6, %7, " \
        " %8, %9, %10, %11, %12, %13, %14, %15, " \
        " %16, %17, %18, %19, %20, %21, %22, %23, " \
        " %24, %25, %26, %27, %28, %29, %30, %31}, [%32];" \
        : "=r"((r)[0]),  "=r"((r)[1]),  "=r"((r)[2]),  "=r"((r)[3]), \
          "=r"((r)[4]),  "=r"((r)[5]),  "=r"((r)[6]),  "=r"((r)[7]), \
          "=r"((r)[8]),  "=r"((r)[9]),  "=r"((r)[10]), "=r"((r)[11]), \
          "=r"((r)[12]), "=r"((r)[13]), "=r"((r)[14]), "=r"((r)[15]), \
          "=r"((r)[16]), "=r"((r)[17]), "=r"((r)[18]), "=r"((r)[19]), \
          "=r"((r)[20]), "=r"((r)[21]), "=r"((r)[22]), "=r"((r)[23]), \
          "=r"((r)[24]), "=r"((r)[25]), "=r"((r)[26]), "=r"((r)[27]), \
          "=r"((r)[28]), "=r"((r)[29]), "=r"((r)[30]), "=r"((r)[31]) \
        : "r"(tmem))

// SW128 K-major SMEM descriptor (layout=2, version=1, SBO=64, LBO=1)
static __device__ __forceinline__ uint64_t make_desc(uint32_t addr) {
    return ((uint64_t)2 << 61) | ((uint64_t)1 << 46) | ((uint64_t)64 << 32)
         | ((uint64_t)1 << 16) | (uint64_t)((addr >> 4) & 0x3FFF);
}
__device__ __forceinline__ uint32_t sw128(uint32_t off) { return off ^ ((off >> 3) & 0x70); }

// blocked-atom byte offset for bf16 K-major tile, 128 rows x 128 K-cols
__device__ __forceinline__ uint32_t bf16_off(int row, int col) {
    uint32_t off = (uint32_t)(((row >> 3) + (col >> 6) * 16) * 1024 + (row & 7) * 128 + (col & 63) * 2);
    return sw128(off);
}

#if defined(__CUDA_ARCH_FEAT_SM103_ALL) || !defined(__CUDA_ARCH__)
__device__ __forceinline__ void mma_f16_ss(uint32_t d, uint64_t ad, uint64_t bd,
                                           uint32_t idesc, bool acc) {
    uint32_t en = acc ? 1u : 0u;
    asm volatile(
        "{\n\t.reg .pred p;\n\tsetp.ne.u32 p, %5, 0;\n\t"
        "tcgen05.mma.cta_group::1.kind::f16 [%0], %1, %2, %3, {%4, %4, %4, %4}, p;\n\t}"
        :: "r"(d), "l"(ad), "l"(bd), "r"(idesc), "r"(0u), "r"(en) : "memory");
}
#endif

// idesc: dtype=F32, atype=BF16, btype=BF16, N=128, M=128
#define MMA_IDESC ((1u << 4) | (1u << 7) | (1u << 10) | (16u << 17) | (8u << 24))

// split helper: fp32 -> (hi, lo) bf16
__device__ __forceinline__ void bsplit(float v, __nv_bfloat16& h, __nv_bfloat16& l) {
    h = __float2bfloat16_rn(v);
    l = __float2bfloat16_rn(v - __bfloat162float(h));
}

// ---------------- batchnorm stats (d_stats zeroed by k_prep / static init) --------
__global__ void k_stats_s(const float* __restrict__ sx, int rows) {
    const float4* v4 = (const float4*)sx;
    float s0 = 0, s1 = 0, s2 = 0, s3 = 0, q0 = 0, q1 = 0, q2 = 0, q3 = 0;
    for (int r = blockIdx.x * blockDim.x + threadIdx.x; r < rows; r += gridDim.x * blockDim.x) {
        float4 v = v4[r];
        s0 += v.x; q0 += v.x * v.x;
        s1 += v.y; q1 += v.y * v.y;
        s2 += v.z; q2 += v.z * v.z;
        s3 += v.w; q3 += v.w * v.w;
    }
    #pragma unroll
    for (int off = 16; off > 0; off >>= 1) {
        s0 += __shfl_down_sync(0xffffffffu, s0, off);
        s1 += __shfl_down_sync(0xffffffffu, s1, off);
        s2 += __shfl_down_sync(0xffffffffu, s2, off);
        s3 += __shfl_down_sync(0xffffffffu, s3, off);
        q0 += __shfl_down_sync(0xffffffffu, q0, off);
        q1 += __shfl_down_sync(0xffffffffu, q1, off);
        q2 += __shfl_down_sync(0xffffffffu, q2, off);
        q3 += __shfl_down_sync(0xffffffffu, q3, off);
    }
    if ((threadIdx.x & 31) == 0) {
        atomicAdd(&d_stats[0], s0); atomicAdd(&d_stats[1], s1);
        atomicAdd(&d_stats[2], s2); atomicAdd(&d_stats[3], s3);
        atomicAdd(&d_stats[4], q0); atomicAdd(&d_stats[5], q1);
        atomicAdd(&d_stats[6], q2); atomicAdd(&d_stats[7], q3);
    }
}

__global__ void k_stats_r(const float* __restrict__ rx, int rows) {
    const float4* v4 = (const float4*)rx;
    float s0 = 0, s1 = 0, s2 = 0, q0 = 0, q1 = 0, q2 = 0;
    for (int r = blockIdx.x * blockDim.x + threadIdx.x; r < rows; r += gridDim.x * blockDim.x) {
        float4 v = v4[r * 2];
        s0 += v.x; q0 += v.x * v.x;
        s1 += v.y; q1 += v.y * v.y;
        s2 += v.z; q2 += v.z * v.z;
    }
    #pragma unroll
    for (int off = 16; off > 0; off >>= 1) {
        s0 += __shfl_down_sync(0xffffffffu, s0, off);
        s1 += __shfl_down_sync(0xffffffffu, s1, off);
        s2 += __shfl_down_sync(0xffffffffu, s2, off);
        q0 += __shfl_down_sync(0xffffffffu, q0, off);
        q1 += __shfl_down_sync(0xffffffffu, q1, off);
        q2 += __shfl_down_sync(0xffffffffu, q2, off);
    }
    if ((threadIdx.x & 31) == 0) {
        atomicAdd(&d_stats[8],  s0); atomicAdd(&d_stats[9],  s1);
        atomicAdd(&d_stats[10], s2); atomicAdd(&d_stats[11], q0);
        atomicAdd(&d_stats[12], q1); atomicAdd(&d_stats[13], q2);
    }
}

// computes bn scale/shift, then re-zeroes d_stats for the next graph replay
__global__ void k_prep(const float* __restrict__ bsw, const float* __restrict__ bsb,
                       const float* __restrict__ brw, const float* __restrict__ brb,
                       int ns, int nr) {
    int t = threadIdx.x;
    if (t < 4) {
        float m = d_stats[t] / (float)ns;
        float var = d_stats[4 + t] / (float)ns - m * m;
        float sc = rsqrtf(var + 1e-5f) * bsw[t];
        d_pre[t] = sc;
        d_pre[4 + t] = bsb[t] - m * sc;
    } else if (t < 7) {
        int c = t - 4;
        float m = d_stats[8 + c] / (float)nr;
        float var = d_stats[11 + c] / (float)nr - m * m;
        float sc = rsqrtf(var + 1e-5f) * brw[c];
        d_pre[8 + c] = sc;
        d_pre[11 + c] = brb[c] - m * sc;
    }
    __syncthreads();
    if (t < 16) d_stats[t] = 0.f;
}

// -------- feature encoder (warp-per-node, bn folded into smem weights) + o-branch --
// blocks [0, nbF): 8 nodes each (one per warp). blocks [nbF, nbF+Bn): o-branch.
__global__ void __launch_bounds__(256) k_featO(
        const float* __restrict__ sx, const float* __restrict__ rx,
        const float* __restrict__ wsl, const float* __restrict__ wrl,
        const float* __restrict__ w1, const float* __restrict__ b1,
        const float* __restrict__ w2, const float* __restrict__ b2,
        int n, int nbF) {
    int tid = threadIdx.x;
    if ((int)blockIdx.x < nbF) {
        __shared__ float ws[SC_ * HC_];   // scaled s-weights
        __shared__ float wr[RC_ * HC_];   // scaled r-weights
        __shared__ float bs[HC_], br[HC_];
        for (int i = tid; i < SC_ * HC_; i += 256)
            ws[i] = __ldg(wsl + i) * d_pre[i >> 7];
        for (int i = tid; i < RC_ * HC_; i += 256)
            wr[i] = __ldg(wrl + i) * d_pre[8 + (i >> 7)];
        if (tid < HC_) {
            float as = 0.f, ar = 0.f;
            #pragma unroll
            for (int c = 0; c < SC_; c++) as += d_pre[4 + c] * __ldg(wsl + c * HC_ + tid);
            #pragma unroll
            for (int c = 0; c < RC_; c++) ar += d_pre[11 + c] * __ldg(wrl + c * HC_ + tid);
            bs[tid] = as;
            br[tid] = ar;
        }
        __syncthreads();
        int wid = tid >> 5, lane = tid & 31;
        int node = blockIdx.x * 8 + wid;
        if (node >= n) return;
        int b = node / (S_ + R_);
        int pos = node - b * (S_ + R_);
        float4 xv = make_float4(0.f, 0.f, 0.f, 0.f);
        if (lane == 0) {
            if (pos < S_) xv = ((const float4*)sx)[b * S_ + pos];
            else          xv = ((const float4*)rx)[(size_t)(b * R_ + pos - S_) * 2];
        }
        float x0 = __shfl_sync(0xffffffffu, xv.x, 0);
        float x1 = __shfl_sync(0xffffffffu, xv.y, 0);
        float x2 = __shfl_sync(0xffffffffu, xv.z, 0);
        float x3 = __shfl_sync(0xffffffffu, xv.w, 0);
        float4 a;
        if (pos < S_) {
            float4 w0 = ((float4*)ws)[lane];
            float4 w1v = ((float4*)ws)[32 + lane];
            float4 w2v = ((float4*)ws)[64 + lane];
            float4 w3v = ((float4*)ws)[96 + lane];
            float4 bb = ((float4*)bs)[lane];
            a.x = bb.x + x0 * w0.x + x1 * w1v.x + x2 * w2v.x + x3 * w3v.x;
            a.y = bb.y + x0 * w0.y + x1 * w1v.y + x2 * w2v.y + x3 * w3v.y;
            a.z = bb.z + x0 * w0.z + x1 * w1v.z + x2 * w2v.z + x3 * w3v.z;
            a.w = bb.w + x0 * w0.w + x1 * w1v.w + x2 * w2v.w + x3 * w3v.w;
        } else {
            float4 w0 = ((float4*)wr)[lane];
            float4 w1v = ((float4*)wr)[32 + lane];
            float4 w2v = ((float4*)wr)[64 + lane];
            float4 bb = ((float4*)br)[lane];
            a.x = bb.x + x0 * w0.x + x1 * w1v.x + x2 * w2v.x;
            a.y = bb.y + x0 * w0.y + x1 * w1v.y + x2 * w2v.y;
            a.z = bb.z + x0 * w0.z + x1 * w1v.z + x2 * w2v.z;
            a.w = bb.w + x0 * w0.w + x1 * w1v.w + x2 * w2v.w;
        }
        a.x = leaky(a.x); a.y = leaky(a.y); a.z = leaky(a.z); a.w = leaky(a.w);
        __nv_bfloat16 h0, h1, h2, h3, l0, l1, l2, l3;
        bsplit(a.x, h0, l0); bsplit(a.y, h1, l1);
        bsplit(a.z, h2, l2); bsplit(a.w, h3, l3);
        uint2 hp, lp;
        hp.x = (uint32_t)__bfloat16_as_ushort(h0) | ((uint32_t)__bfloat16_as_ushort(h1) << 16);
        hp.y = (uint32_t)__bfloat16_as_ushort(h2) | ((uint32_t)__bfloat16_as_ushort(h3) << 16);
        lp.x = (uint32_t)__bfloat16_as_ushort(l0) | ((uint32_t)__bfloat16_as_ushort(l1) << 16);
        lp.y = (uint32_t)__bfloat16_as_ushort(l2) | ((uint32_t)__bfloat16_as_ushort(l3) << 16);
        ((uint2*)d_Xh)[(size_t)node * 32 + lane] = hp;
        ((uint2*)d_Xl)[(size_t)node * 32 + lane] = lp;
    } else {
        __shared__ float sh[HC_];
        int b = blockIdx.x - nbF;
        int h = tid;
        if (h < HC_) {
            float acc = b1[h];
            #pragma unroll
            for (int c = 0; c < 5; c++)
                acc += __ldg(rx + (size_t)(b * R_) * (RC_ + 5) + RC_ + c) * __ldg(w1 + c * HC_ + h);
            sh[h] = leaky(acc);
        }
        __syncthreads();
        if (h < NO_) {
            float o = b2[h];
            #pragma unroll 8
            for (int k = 0; k < HC_; k++) o += sh[k] * __ldg(w2 + k * NO_ + h);
            d_O[b * NO_ + h] = o;
        }
    }
}

// ---------------- W split precompute (once; all layers) ----------------
__global__ void k_wsplit(const float* __restrict__ conv_w) {
    int l = blockIdx.x;
    const float* W = conv_w + (size_t)l * HC_ * HC_;
    for (int i = threadIdx.x; i < HC_ * HC_; i += blockDim.x) {
        int k = i >> 7, nn = i & 127;
        float v = __ldg(W + k * 128 + nn);
        __nv_bfloat16 h, lo;
        bsplit(v, h, lo);
        uint32_t off = bf16_off(nn, k);   // B[n][k] = W[k][n]
        *(__nv_bfloat16*)(d_Wh[l] + off) = h;
        *(__nv_bfloat16*)(d_Wl[l] + off) = lo;
    }
}

// ---------------- init / degree / CSR ----------------
__global__ void k_zero(int n) {
    int i = blockIdx.x * blockDim.x + threadIdx.x;
    if (i < n) d_degi[i] = 0;
}

__global__ void k_count(const int* __restrict__ dst, int E) {
    int e = blockIdx.x * blockDim.x + threadIdx.x;
    if (e < E) atomicAdd(&d_degi[dst[e]], 1);
}

// scan1 also emits dinv (folded former k_dinv pass)
__global__ void k_scan1(int n) {
    __shared__ int sh[512];
    int t = threadIdx.x;
    int g = blockIdx.x * 512 + t;
    int v = (g < n) ? d_degi[g] : 0;
    if (g < n) d_dinv[g] = rsqrtf((float)(v + 1));
    sh[t] = v;
    __syncthreads();
    #pragma unroll
    for (int off = 1; off < 512; off <<= 1) {
        int a = sh[t];
        int b = (t >= off) ? sh[t - off] : 0;
        __syncthreads();
        sh[t] = a + b;
        __syncthreads();
    }
    if (g < n) d_offs[g] = sh[t] - v;
    if (t == 511) d_bsum[blockIdx.x] = sh[511];
}

__global__ void k_scan2(int nb) {
    __shared__ int sh[512];
    int t = threadIdx.x;
    int v = (t < nb) ? d_bsum[t] : 0;
    sh[t] = v;
    __syncthreads();
    #pragma unroll
    for (int off = 1; off < 512; off <<= 1) {
        int a = sh[t];
        int b = (t >= off) ? sh[t - off] : 0;
        __syncthreads();
        sh[t] = a + b;
        __syncthreads();
    }
    if (t < nb) d_bsum[t] = sh[t] - v;
}

__global__ void k_scan3(int n) {
    int g = blockIdx.x * blockDim.x + threadIdx.x;
    if (g < n) {
        int o = d_offs[g] + d_bsum[g >> 9];
        d_offs[g] = o;
        d_curs[g] = o;
    }
}

__global__ void k_fill(const int* __restrict__ src, const int* __restrict__ dst, int E) {
    int e = blockIdx.x * blockDim.x + threadIdx.x;
    if (e < E) {
        int s = src[e], d = dst[e];
        int p = atomicAdd(&d_curs[d], 1);
        float nw = d_dinv[s] * d_dinv[d];
        d_edge[p] = make_uint2((uint32_t)s, __float_as_uint(nw));
    }
}

// ====== persistent pipelined tcgen05 2-term GEMM: XWh = fp16(Xh @ (Wh+Wl)) ======
// A = Xh only (bf16); W keeps hi+lo -> D = Xh·Wh + Xh·Wl. Saves the entire Xl
// staging stream (49.5 MB/layer) and 1/3 of MMA dispatches vs the 3-term version.
__global__ void __launch_bounds__(128) k_mma(const float* __restrict__ W, int layer, int n) {
    extern __shared__ char dyn_smem[];
#if defined(__CUDA_ARCH_FEAT_SM103_ALL) || !defined(__CUDA_ARCH__)
    __shared__ uint32_t s_tmem[2];
    __shared__ __align__(8) unsigned long long s_mbar[2];

    char* base = (char*)(((uintptr_t)dyn_smem + 1023) & ~(uintptr_t)1023);
    char* A0h = base;
    char* A1h = base + 32768;
    char* Bh  = base + 65536;
    char* Bl  = base + 98304;   // total 128 KB

    int tid = threadIdx.x, wid = tid >> 5, lane = tid & 31;

    if (wid == 0) TCG_ALLOC(smem_u32(s_tmem), 256);
    if (tid == 0) {
        MBAR_INIT(smem_u32(&s_mbar[0]), 1);
        MBAR_INIT(smem_u32(&s_mbar[1]), 1);
    }
    __syncthreads();
    uint32_t tmem;
    asm volatile("ld.shared.b32 %0, [%1];" : "=r"(tmem) : "r"(smem_u32(s_tmem)));

    // stage pre-split W (coalesced uint4 copy, once per CTA)
    {
        const uint4* gh = (const uint4*)d_Wh[layer];
        const uint4* gl = (const uint4*)d_Wl[layer];
        uint4* sh = (uint4*)Bh;
        uint4* sl = (uint4*)Bl;
        for (int i = tid; i < 2048; i += 128) { sh[i] = gh[i]; sl[i] = gl[i]; }
    }

    const uint64_t bdh = make_desc(smem_u32(Bh));
    const uint64_t bdl = make_desc(smem_u32(Bl));
    const uint4* GXh = (const uint4*)d_Xh;   // row = 16 uint4 (128 bf16)
    __half* XWh = d_XWh;

    int tiles = (n + 127) >> 7;
    uint32_t ph0 = 0, ph1 = 0;
    int j = 0, prev_t = -1;

    for (int t = blockIdx.x; t < tiles; t += gridDim.x, j++) {
        int buf = j & 1;
        char* Ah = buf ? A1h : A0h;
        int row0 = t << 7;

        // --- stage A tile: swizzled uint4 copy (overlaps in-flight MMA[j-1]) ---
        #pragma unroll 4
        for (int i = tid; i < 2048; i += 128) {          // 128 rows x 16 quads
            int row = i >> 4, q = i & 15;
            uint4 vh = make_uint4(0u, 0u, 0u, 0u);
            if (row0 + row < n) {
                size_t gi = (size_t)(row0 + row) * 16 + q;
                vh = __ldg(GXh + gi);
            }
            *(uint4*)(Ah + bf16_off(row, q * 8)) = vh;
        }
        TCG_FENCE_BEFORE();
        __syncthreads();

        // --- wait for MMA[j-1] ---
        if (j > 0) {
            if (buf) { mbar_wait_parity(smem_u32(&s_mbar[0]), ph0); ph0 ^= 1; }
            else     { mbar_wait_parity(smem_u32(&s_mbar[1]), ph1); ph1 ^= 1; }
            TCG_FENCE_AFTER();
        }

        // --- issue MMA[j] ---
        if (wid == 0) {
            TCG_FENCE_AFTER();
            if (elect_one()) {
                FENCE_ASYNC_SHARED();
                uint64_t adh = make_desc(smem_u32(Ah));
                uint32_t D = tmem + buf * 128;
                #pragma unroll
                for (int s = 0; s < 8; s++) {
                    uint64_t off = (uint64_t)((s & 3) * 2 + (s >> 2) * 1024);
                    mma_f16_ss(D, adh + off, bdh + off, MMA_IDESC, s > 0);
                }
                #pragma unroll
                for (int s = 0; s < 8; s++) {
                    uint64_t off = (uint64_t)((s & 3) * 2 + (s >> 2) * 1024);
                    mma_f16_ss(D, adh + off, bdl + off, MMA_IDESC, true);
                }
                TCG_COMMIT(smem_u32(&s_mbar[buf]));
            }
        }

        // --- epilogue for tile j-1 (overlaps MMA[j]); fp16 output ---
        if (j > 0) {
            int prow = (prev_t << 7) + wid * 32 + lane;
            uint32_t Dp = tmem + (1 - buf) * 128;
            uint32_t r[32];
            #pragma unroll
            for (int c0 = 0; c0 < 128; c0 += 32) {
                TCG_LD_32X32B_X32(r, Dp + c0);
                TCG_WAIT_LD();
                if (prow < n) {
                    uint32_t h2[16];
                    #pragma unroll
                    for (int k = 0; k < 16; k++) {
                        __half2 p = __floats2half2_rn(__uint_as_float(r[2 * k]),
                                                      __uint_as_float(r[2 * k + 1]));
                        h2[k] = *(uint32_t*)&p;
                    }
                    uint4* dst = (uint4*)(XWh + (size_t)prow * 128 + c0);
                    dst[0] = make_uint4(h2[0], h2[1], h2[2], h2[3]);
                    dst[1] = make_uint4(h2[4], h2[5], h2[6], h2[7]);
                    dst[2] = make_uint4(h2[8], h2[9], h2[10], h2[11]);
                    dst[3] = make_uint4(h2[12], h2[13], h2[14], h2[15]);
                }
            }
            TCG_FENCE_BEFORE();
        }
        prev_t = t;
    }

    // --- drain last tile ---
    if (j > 0) {
        int buf = (j - 1) & 1;
        if (buf) { mbar_wait_parity(smem_u32(&s_mbar[1]), ph1); ph1 ^= 1; }
        else     { mbar_wait_parity(smem_u32(&s_mbar[0]), ph0); ph0 ^= 1; }
        TCG_FENCE_AFTER();
        int prow = (prev_t << 7) + wid * 32 + lane;
        uint32_t Dp = tmem + buf * 128;
        uint32_t r[32];
        #pragma unroll
        for (int c0 = 0; c0 < 128; c0 += 32) {
            TCG_LD_32X32B_X32(r, Dp + c0);
            TCG_WAIT_LD();
            if (prow < n) {
                uint32_t h2[16];
                #pragma unroll
                for (int k = 0; k < 16; k++) {
                    __half2 p = __floats2half2_rn(__uint_as_float(r[2 * k]),
                                                  __uint_as_float(r[2 * k + 1]));
                    h2[k] = *(uint32_t*)&p;
                }
                uint4* dst = (uint4*)(XWh + (size_t)prow * 128 + c0);
                dst[0] = make_uint4(h2[0], h2[1], h2[2], h2[3]);
                dst[1] = make_uint4(h2[4], h2[5], h2[6], h2[7]);
                dst[2] = make_uint4(h2[8], h2[9], h2[10], h2[11]);
                dst[3] = make_uint4(h2[12], h2[13], h2[14], h2[15]);
            }
        }
        TCG_FENCE_BEFORE();
    }
    __syncthreads();
    if (wid == 0) {
        if (elect_one()) {
            MBAR_INVAL(smem_u32(&s_mbar[0]));
            MBAR_INVAL(smem_u32(&s_mbar[1]));
        }
        TCG_RELINQ();
        TCG_DEALLOC(tmem, 256);
    }
#else
    // fp32 fallback for the non-'a' gencode pass (never selected at runtime on GB300)
    float* Ws = (float*)(((uintptr_t)dyn_smem + 1023) & ~(uintptr_t)1023);  // 64 KB
    int tid = threadIdx.x;
    for (int i = tid; i < 128 * 128; i += 128) Ws[i] = __ldg(W + i);
    __syncthreads();
    int tiles = (n + 127) >> 7;
    for (int t = blockIdx.x; t < tiles; t += gridDim.x) {
        int row = (t << 7) + tid;
        if (row < n) {
            for (int c0 = 0; c0 < 128; c0 += 16) {
                float acc[16];
                #pragma unroll
                for (int jj = 0; jj < 16; jj++) acc[jj] = 0.f;
                for (int k = 0; k < 128; k++) {
                    float a = __bfloat162float(d_Xh[(size_t)row * 128 + k]);
                    #pragma unroll
                    for (int jj = 0; jj < 16; jj++) acc[jj] += a * Ws[k * 128 + c0 + jj];
                }
                #pragma unroll
                for (int jj = 0; jj < 16; jj++)
                    d_XWh[(size_t)row * 128 + c0 + jj] = __float2half_rn(acc[jj]);
            }
        }
    }
#endif
}

// ------- fused gather(fp16 XW) + self-loop + bias + leaky + residual (+pool) -------
__global__ void k_gather(const float* __restrict__ bias, int n, int last) {
    int warp = (blockIdx.x * blockDim.x + threadIdx.x) >> 5;
    int lane = threadIdx.x & 31;
    if (warp >= n) return;
    int cnt = d_degi[warp];
    int start = d_offs[warp];
    float di = d_dinv[warp];
    const uint2* xw2 = (const uint2*)d_XWh;   // 4 halves per uint2; row stride 32

    // self loop
    uint2 sp = xw2[(size_t)warp * 32 + lane];
    float2 sa = __half22float2(*(__half2*)&sp.x);
    float2 sb = __half22float2(*(__half2*)&sp.y);
    float ns = di * di;
    float4 acc = make_float4(sa.x * ns, sa.y * ns, sb.x * ns, sb.y * ns);

    int j = 0;
    for (; j + 4 <= cnt; j += 4) {
        uint2 e0 = __ldg(d_edge + start + j);
        uint2 e1 = __ldg(d_edge + start + j + 1);
        uint2 e2 = __ldg(d_edge + start + j + 2);
        uint2 e3 = __ldg(d_edge + start + j + 3);
        uint2 v0 = __ldg(xw2 + (size_t)e0.x * 32 + lane);
        uint2 v1 = __ldg(xw2 + (size_t)e1.x * 32 + lane);
        uint2 v2 = __ldg(xw2 + (size_t)e2.x * 32 + lane);
        uint2 v3 = __ldg(xw2 + (size_t)e3.x * 32 + lane);
        float n0 = __uint_as_float(e0.y), n1 = __uint_as_float(e1.y);
        float n2 = __uint_as_float(e2.y), n3 = __uint_as_float(e3.y);
        float2 a0 = __half22float2(*(__half2*)&v0.x), b0 = __half22float2(*(__half2*)&v0.y);
        float2 a1 = __half22float2(*(__half2*)&v1.x), b1 = __half22float2(*(__half2*)&v1.y);
        float2 a2 = __half22float2(*(__half2*)&v2.x), b2 = __half22float2(*(__half2*)&v2.y);
        float2 a3 = __half22float2(*(__half2*)&v3.x), b3 = __half22float2(*(__half2*)&v3.y);
        acc.x += n0 * a0.x + n1 * a1.x + n2 * a2.x + n3 * a3.x;
        acc.y += n0 * a0.y + n1 * a1.y + n2 * a2.y + n3 * a3.y;
        acc.z += n0 * b0.x + n1 * b1.x + n2 * b2.x + n3 * b3.x;
        acc.w += n0 * b0.y + n1 * b1.y + n2 * b2.y + n3 * b3.y;
    }
    for (; j < cnt; j++) {
        uint2 e0 = __ldg(d_edge + start + j);
        uint2 v0 = __ldg(xw2 + (size_t)e0.x * 32 + lane);
        float n0 = __uint_as_float(e0.y);
        float2 a0 = __half22float2(*(__half2*)&v0.x), b0 = __half22float2(*(__half2*)&v0.y);
        acc.x += n0 * a0.x;
        acc.y += n0 * a0.y;
        acc.z += n0 * b0.x;
        acc.w += n0 * b0.y;
    }

    float4 bv = ((const float4*)bias)[lane];
    acc.x = leaky(acc.x + bv.x);
    acc.y = leaky(acc.y + bv.y);
    acc.z = leaky(acc.z + bv.z);
    acc.w = leaky(acc.w + bv.w);

    // residual from bf16 hi/lo pair
    uint2 xh = __ldg(((const uint2*)d_Xh) + (size_t)warp * 32 + lane);
    uint2 xl = __ldg(((const uint2*)d_Xl) + (size_t)warp * 32 + lane);
    __nv_bfloat162 h01 = *(__nv_bfloat162*)&xh.x, h23 = *(__nv_bfloat162*)&xh.y;
    __nv_bfloat162 l01 = *(__nv_bfloat162*)&xl.x, l23 = *(__nv_bfloat162*)&xl.y;
    float4 nx;
    nx.x = __bfloat162float(h01.x) + __bfloat162float(l01.x) + acc.x;
    nx.y = __bfloat162float(h01.y) + __bfloat162float(l01.y) + acc.y;
    nx.z = __bfloat162float(h23.x) + __bfloat162float(l23.x) + acc.z;
    nx.w = __bfloat162float(h23.y) + __bfloat162float(l23.y) + acc.w;

    if (last) {
        // fused mean-pool: sum across 128 channels -> /128
        float s = nx.x + nx.y + nx.z + nx.w;
        #pragma unroll
        for (int off = 16; off > 0; off >>= 1) s += __shfl_down_sync(0xffffffffu, s, off);
        if (lane == 0) d_pooled[warp] = s * (1.f / (float)HC_);
    } else {
        __nv_bfloat16 h0, h1, h2, h3, l0, l1, l2, l3;
        bsplit(nx.x, h0, l0); bsplit(nx.y, h1, l1);
        bsplit(nx.z, h2, l2); bsplit(nx.w, h3, l3);
        uint2 hp, lp;
        hp.x = (uint32_t)__bfloat16_as_ushort(h0) | ((uint32_t)__bfloat16_as_ushort(h1) << 16);
        hp.y = (uint32_t)__bfloat16_as_ushort(h2) | ((uint32_t)__bfloat16_as_ushort(h3) << 16);
        lp.x = (uint32_t)__bfloat16_as_ushort(l0) | ((uint32_t)__bfloat16_as_ushort(l1) << 16);
        lp.y = (uint32_t)__bfloat16_as_ushort(l2) | ((uint32_t)__bfloat16_as_ushort(l3) << 16);
        ((uint2*)d_Xh)[(size_t)warp * 32 + lane] = hp;
        ((uint2*)d_Xl)[(size_t)warp * 32 + lane] = lp;
    }
}

// ---------------- readout ----------------
__global__ void k_final(const float* __restrict__ lw, const float* __restrict__ lb,
                        float* __restrict__ out) {
    __shared__ float sh[128 * NO_];
    int b = blockIdx.x, t = threadIdx.x;
    float acc[NO_];
    #pragma unroll
    for (int j = 0; j < NO_; j++) acc[j] = 0.f;
    for (int tt = t; tt < S_ + R_; tt += 128) {
        float p = d_pooled[b * (S_ + R_) + tt];
        #pragma unroll
        for (int j = 0; j < NO_; j++) acc[j] += p * __ldg(lw + tt * NO_ + j);
    }
    #pragma unroll
    for (int j = 0; j < NO_; j++) sh[t * NO_ + j] = acc[j];
    __syncthreads();
    for (int off = 64; off > 0; off >>= 1) {
        if (t < off) {
            #pragma unroll
            for (int j = 0; j < NO_; j++) sh[t * NO_ + j] += sh[(t + off) * NO_ + j];
        }
        __syncthreads();
    }
    if (t == 0) {
        float z[NO_], sum = 0.f;
        #pragma unroll
        for (int j = 0; j < NO_; j++) { z[j] = expf(sh[j] + lb[j]); sum += z[j]; }
        float inv = 1.f / (sum + 1.f);
        #pragma unroll
        for (int j = 0; j < NO_; j++)
            out[b * NO_ + j] = z[j] * inv * expf(d_O[b * NO_ + j]);
    }
}

// ---------------- host orchestration (fork-join: CSR+wsplit overlap encoder) ------
extern "C" void kernel_launch(void* const* d_in, const int* in_sizes, int n_in,
                              void* d_out, int out_size) {
    const float* s_x     = (const float*)d_in[0];
    const float* r_x     = (const float*)d_in[1];
    const int*   ei      = (const int*)d_in[2];
    const float* bn_s_w  = (const float*)d_in[3];
    const float* bn_s_b  = (const float*)d_in[4];
    const float* bn_r_w  = (const float*)d_in[5];
    const float* bn_r_b  = (const float*)d_in[6];
    const float* lin_s_w = (const float*)d_in[7];
    const float* lin_r_w = (const float*)d_in[8];
    const float* conv_w  = (const float*)d_in[9];
    const float* conv_b  = (const float*)d_in[10];
    const float* linr_w  = (const float*)d_in[11];
    const float* linr_b  = (const float*)d_in[12];
    const float* lino_w1 = (const float*)d_in[13];
    const float* lino_b1 = (const float*)d_in[14];
    const float* lino_w2 = (const float*)d_in[15];
    const float* lino_b2 = (const float*)d_in[16];
    float* out = (float*)d_out;

    int E  = in_sizes[2] / 2;
    int Bn = in_sizes[1] / (R_ * (RC_ + 5));
    int n  = Bn * (S_ + R_);
    int rowsS = Bn * S_, rowsR = Bn * R_;
    const int* src = ei;
    const int* dst = ei + E;

    static const int MMA_SMEM = 4 * 32768 + 1024;   // 129 KB (1 CTA/SM, persistent)

    // one-time infra init (streams/events; no device memory involved)
    static cudaStream_t sB = 0;
    static cudaEvent_t evFork = 0, evJoin = 0;
    static bool inited = false;
    if (!inited) {
        cudaFuncSetAttribute(k_mma, cudaFuncAttributeMaxDynamicSharedMemorySize, MMA_SMEM);
        if (cudaStreamCreateWithFlags(&sB, cudaStreamNonBlocking) != cudaSuccess) sB = 0;
        if (sB) {
            if (cudaEventCreateWithFlags(&evFork, cudaEventDisableTiming) != cudaSuccess ||
                cudaEventCreateWithFlags(&evJoin, cudaEventDisableTiming) != cudaSuccess) {
                sB = 0;
            }
        }
        inited = true;
    }

    int nbF = (n + 7) / 8;
    int nb1 = (n + 511) / 512;
    bool fork = (sB != 0);

    // ---- fork: wsplit + CSR chain on side stream (independent of encoder) ----
    if (fork) {
        cudaEventRecord(evFork, 0);
        cudaStreamWaitEvent(sB, evFork, 0);
        k_wsplit<<<L_, 256, 0, sB>>>(conv_w);
        k_zero<<<(n + 255) / 256, 256, 0, sB>>>(n);
        k_count<<<(E + 255) / 256, 256, 0, sB>>>(dst, E);
        k_scan1<<<nb1, 512, 0, sB>>>(n);
        k_scan2<<<1, 512, 0, sB>>>(nb1);
        k_scan3<<<(n + 255) / 256, 256, 0, sB>>>(n);
        k_fill<<<(E + 255) / 256, 256, 0, sB>>>(src, dst, E);
        cudaEventRecord(evJoin, sB);
    }

    // ---- main stream: encoder chain ----
    k_stats_s<<<96, 256>>>(s_x, rowsS);
    k_stats_r<<<192, 256>>>(r_x, rowsR);
    k_prep<<<1, 32>>>(bn_s_w, bn_s_b, bn_r_w, bn_r_b, rowsS, rowsR);
    k_featO<<<nbF + Bn, 256>>>(s_x, r_x, lin_s_w, lin_r_w,
                               lino_w1, lino_b1, lino_w2, lino_b2, n, nbF);

    if (fork) {
        cudaStreamWaitEvent(0, evJoin, 0);   // wsplit needed by mma0; CSR by gather0
    } else {
        k_wsplit<<<L_, 256>>>(conv_w);
        k_zero<<<(n + 255) / 256, 256>>>(n);
        k_count<<<(E + 255) / 256, 256>>>(dst, E);
        k_scan1<<<nb1, 512>>>(n);
        k_scan2<<<1, 512>>>(nb1);
        k_scan3<<<(n + 255) / 256, 256>>>(n);
        k_fill<<<(E + 255) / 256, 256>>>(src, dst, E);
    }

    // ---- layers ----
    int gather_blocks = (n * 32 + 255) / 256;
    for (int l = 0; l < L_; l++) {
        k_mma<<<148, 128, MMA_SMEM>>>(conv_w + (size_t)l * HC_ * HC_, l, n);
        k_gather<<<gather_blocks, 256>>>(conv_b + l * HC_, n, l == L_ - 1);
    }

    // readout (pool fused into last gather)
    k_final<<<Bn, 128>>>(linr_w, linr_b, out);
}